// round 1
// baseline (speedup 1.0000x reference)
#include <cuda_runtime.h>
#include <cstdint>
#include <math.h>

// Problem dims
#define BB 4
#define TT 1024
#define CC 1024
#define HH 16
#define DD 64
#define FF 4096
#define MR 4096   // B*T

// ---------------------------------------------------------------------------
// Scratch (static device globals — no runtime allocation allowed)
// ---------------------------------------------------------------------------
__device__ float g_h   [MR * CC];        // ln1 output
__device__ float g_wqkv[CC * 3 * CC];    // packed qkv weights (C x 3C)
__device__ float g_qkv [MR * 3 * CC];    // q|k|v per token
__device__ float g_att [MR * CC];        // attention output (heads concat)
__device__ float g_proj[MR * CC];        // Wo projection output
__device__ float g_h2  [MR * CC];        // ln2 output
__device__ float g_ffn1[MR * FF];        // relu(h2 @ W1 + b1)
__device__ int   g_mask[MR];             // expanded padding mask per (b,t)

// ---------------------------------------------------------------------------
// Padding-mask dtype classification + expansion.
// The mask may arrive as bool8, int32, or float32. Classify from bit patterns
// of the first 4096 bytes (safe to read under every interpretation), then
// expand to int.
// ---------------------------------------------------------------------------
__global__ void mask_expand_kernel(const void* __restrict__ pm, int* __restrict__ out)
{
    int tid = threadIdx.x;
    const unsigned* w = (const unsigned*)pm;
    int li = 0, lf = 0;
    for (int i = tid; i < 1024; i += 256) {
        unsigned v = w[i];
        li |= (v > 1u);                            // not int32 {0,1}
        lf |= (v != 0u && v != 0x3F800000u);       // not float32 {0.0,1.0}
    }
    int not_int = __syncthreads_or(li);
    int not_flt = __syncthreads_or(lf);
    int cls = (!not_int) ? 0 : ((!not_flt) ? 1 : 2);
    for (int i = tid; i < MR; i += 256) {
        int m;
        if (cls == 0)      m = (((const int*)pm)[i] != 0);
        else if (cls == 1) m = (((const float*)pm)[i] != 0.0f);
        else               m = (((const unsigned char*)pm)[i] != 0);
        out[i] = m;
    }
}

// ---------------------------------------------------------------------------
// Pack Wq/Wk/Wv (each (H, C, D)) into a single (C, 3C) row-major matrix:
// col j: [0,1024) -> q head j/64 dim j%64; [1024,2048) -> k; [2048,3072) -> v
// ---------------------------------------------------------------------------
__global__ void pack_qkv_kernel(const float* __restrict__ Wq,
                                const float* __restrict__ Wk,
                                const float* __restrict__ Wv,
                                float* __restrict__ out)
{
    int idx = blockIdx.x * blockDim.x + threadIdx.x;
    if (idx >= CC * 3 * CC) return;
    int c = idx / (3 * CC);
    int j = idx % (3 * CC);
    const float* W = (j < CC) ? Wq : (j < 2 * CC) ? Wk : Wv;
    int jj = j & (CC - 1);
    int h = jj >> 6, d = jj & 63;
    out[idx] = W[(h * CC + c) * DD + d];
}

// ---------------------------------------------------------------------------
// LayerNorm: one block (256 threads) per row of 1024.
// ---------------------------------------------------------------------------
__global__ __launch_bounds__(256) void ln_kernel(const float* __restrict__ x,
                                                 const float* __restrict__ g,
                                                 const float* __restrict__ b,
                                                 float* __restrict__ out)
{
    int row = blockIdx.x, tid = threadIdx.x;
    const float* xr = x + row * CC;
    float v[4];
    float s = 0.f, ss = 0.f;
#pragma unroll
    for (int i = 0; i < 4; i++) {
        v[i] = xr[tid + i * 256];
        s += v[i];
        ss += v[i] * v[i];
    }
#pragma unroll
    for (int o = 16; o; o >>= 1) {
        s  += __shfl_xor_sync(0xffffffffu, s,  o);
        ss += __shfl_xor_sync(0xffffffffu, ss, o);
    }
    __shared__ float ws[8], wss[8];
    __shared__ float s_m, s_r;
    int wid = tid >> 5;
    if ((tid & 31) == 0) { ws[wid] = s; wss[wid] = ss; }
    __syncthreads();
    if (tid == 0) {
        float S = 0.f, SS = 0.f;
        for (int i = 0; i < 8; i++) { S += ws[i]; SS += wss[i]; }
        float m = S * (1.0f / CC);
        float var = SS * (1.0f / CC) - m * m;
        s_m = m;
        s_r = rsqrtf(var + 1e-5f);
    }
    __syncthreads();
    float m = s_m, r = s_r;
    float* orow = out + row * CC;
#pragma unroll
    for (int i = 0; i < 4; i++) {
        int c = tid + i * 256;
        orow[c] = (v[i] - m) * r * g[c] + b[c];
    }
}

// ---------------------------------------------------------------------------
// fp32 SGEMM: C = A(MxK) @ B(KxN) [+ bias] [relu]. 128x128x8 tiles, 8x8/thread.
// M,N multiples of 128; K multiple of 8 (all true here).
// ---------------------------------------------------------------------------
__global__ __launch_bounds__(256) void sgemm_kernel(const float* __restrict__ A,
                                                    const float* __restrict__ B,
                                                    const float* __restrict__ bias,
                                                    float* __restrict__ C,
                                                    int M, int N, int K, int relu)
{
    __shared__ __align__(16) float As[8][128];
    __shared__ __align__(16) float Bs[8][128];
    int tid = threadIdx.x;
    int bm = blockIdx.y * 128, bn = blockIdx.x * 128;
    int a_row = tid >> 1, a_col = (tid & 1) * 4;
    int b_row = tid >> 5, b_col = (tid & 31) * 4;
    const float* Aptr = A + (bm + a_row) * K + a_col;
    const float* Bptr = B + b_row * N + bn + b_col;
    float acc[8][8] = {};
    int ty = tid >> 4, tx = tid & 15;
    int row0 = ty * 8, col0 = tx * 8;

    for (int k0 = 0; k0 < K; k0 += 8) {
        float4 av = *(const float4*)(Aptr + k0);
        As[a_col + 0][a_row] = av.x;
        As[a_col + 1][a_row] = av.y;
        As[a_col + 2][a_row] = av.z;
        As[a_col + 3][a_row] = av.w;
        *(float4*)&Bs[b_row][b_col] = *(const float4*)(Bptr + k0 * N);
        __syncthreads();
#pragma unroll
        for (int kk = 0; kk < 8; kk++) {
            float4 a0 = *(float4*)&As[kk][row0];
            float4 a1 = *(float4*)&As[kk][row0 + 4];
            float4 b0 = *(float4*)&Bs[kk][col0];
            float4 b1 = *(float4*)&Bs[kk][col0 + 4];
            float ar[8] = {a0.x, a0.y, a0.z, a0.w, a1.x, a1.y, a1.z, a1.w};
            float br[8] = {b0.x, b0.y, b0.z, b0.w, b1.x, b1.y, b1.z, b1.w};
#pragma unroll
            for (int i = 0; i < 8; i++)
#pragma unroll
                for (int j = 0; j < 8; j++)
                    acc[i][j] += ar[i] * br[j];
        }
        __syncthreads();
    }

#pragma unroll
    for (int i = 0; i < 8; i++) {
        float* crow = C + (bm + row0 + i) * N + bn + col0;
#pragma unroll
        for (int j = 0; j < 8; j++) {
            float v = acc[i][j];
            if (bias) v += bias[bn + col0 + j];
            if (relu) v = fmaxf(v, 0.0f);
            crow[j] = v;
        }
    }
}

// ---------------------------------------------------------------------------
// Attention: flash-style online softmax over the FULL sequence (the padding
// mask makes future padded columns finite (-1e9), so they cannot be skipped —
// rows whose entire causal prefix is padded softmax uniformly over ALL padded
// columns, including future ones).
// Grid: (T/64, B*H). 64 query rows per block, 64-wide s tiles.
// Thread (ty,tx) (16x16) owns a 4x4 register tile.
// ---------------------------------------------------------------------------
#define APAD 68
__global__ __launch_bounds__(256) void attn_kernel(const float* __restrict__ qkv,
                                                   const int* __restrict__ mask,
                                                   float* __restrict__ outp)
{
    extern __shared__ __align__(16) float sm[];
    float* Qt = sm;                 // [64][APAD]  Qt[d][r] (d-major)
    float* Kt = sm + 64 * APAD;     // [64][APAD]  Kt[d][s] (d-major)
    float* Vs = sm + 2 * 64 * APAD; // [64][APAD]  Vs[s][d]
    float* Pt = sm + 3 * 64 * APAD; // [64][APAD]  Pt[s][r]

    int bh = blockIdx.y;
    int b = bh >> 4, h = bh & 15;
    int qt0 = blockIdx.x * 64;
    int tid = threadIdx.x;
    int ty = tid >> 4, tx = tid & 15;

    const float* base = qkv + (b * TT) * (3 * CC) + h * DD;

    // load Q tile, transposed to d-major
    for (int i = tid; i < 4096; i += 256) {
        int r = i >> 6, d = i & 63;
        Qt[d * APAD + r] = base[(qt0 + r) * (3 * CC) + d];
    }

    float mrow[4], lrow[4], O[4][4];
#pragma unroll
    for (int i = 0; i < 4; i++) {
        mrow[i] = -INFINITY;
        lrow[i] = 0.0f;
#pragma unroll
        for (int j = 0; j < 4; j++) O[i][j] = 0.0f;
    }
    const int* mrowp = mask + b * TT;

    for (int st0 = 0; st0 < TT; st0 += 64) {
        __syncthreads();   // protect Kt/Vs (and first-iter Qt visibility)
        for (int i = tid; i < 4096; i += 256) {
            int r = i >> 6, d = i & 63;
            Kt[d * APAD + r] = base[(st0 + r) * (3 * CC) + CC + d];
            Vs[r * APAD + d] = base[(st0 + r) * (3 * CC) + 2 * CC + d];
        }
        __syncthreads();

        // S = Q K^T (4x4 per thread)
        float acc[4][4] = {};
#pragma unroll 8
        for (int d = 0; d < 64; d++) {
            float4 q4 = *(float4*)&Qt[d * APAD + ty * 4];
            float4 k4 = *(float4*)&Kt[d * APAD + tx * 4];
            float qa[4] = {q4.x, q4.y, q4.z, q4.w};
            float ka[4] = {k4.x, k4.y, k4.z, k4.w};
#pragma unroll
            for (int i = 0; i < 4; i++)
#pragma unroll
                for (int j = 0; j < 4; j++)
                    acc[i][j] += qa[i] * ka[j];
        }

        // scale + causal(-inf) then padding(-1e9) — faithful order
#pragma unroll
        for (int i = 0; i < 4; i++) {
            int t = qt0 + ty * 4 + i;
#pragma unroll
            for (int j = 0; j < 4; j++) {
                int s = st0 + tx * 4 + j;
                float v = acc[i][j] * 0.03125f;   // C^-0.5 = 1/32
                if (s > t) v = -INFINITY;
                if (mrowp[s]) v = -1e9f;
                acc[i][j] = v;
            }
        }

        // online softmax update per row
#pragma unroll
        for (int i = 0; i < 4; i++) {
            float mt = fmaxf(fmaxf(acc[i][0], acc[i][1]), fmaxf(acc[i][2], acc[i][3]));
            mt = fmaxf(mt, __shfl_xor_sync(0xffffffffu, mt, 1));
            mt = fmaxf(mt, __shfl_xor_sync(0xffffffffu, mt, 2));
            mt = fmaxf(mt, __shfl_xor_sync(0xffffffffu, mt, 4));
            mt = fmaxf(mt, __shfl_xor_sync(0xffffffffu, mt, 8));
            float mn = fmaxf(mrow[i], mt);          // finite after first tile
            float f = __expf(mrow[i] - mn);         // exp(-inf)=0 on first tile
            float ps = 0.0f;
#pragma unroll
            for (int j = 0; j < 4; j++) {
                float p = __expf(acc[i][j] - mn);
                acc[i][j] = p;
                ps += p;
            }
            ps += __shfl_xor_sync(0xffffffffu, ps, 1);
            ps += __shfl_xor_sync(0xffffffffu, ps, 2);
            ps += __shfl_xor_sync(0xffffffffu, ps, 4);
            ps += __shfl_xor_sync(0xffffffffu, ps, 8);
            lrow[i] = lrow[i] * f + ps;
            mrow[i] = mn;
#pragma unroll
            for (int j = 0; j < 4; j++) O[i][j] *= f;
        }

        // write P transposed (Pt[s][r]) for the O phase
#pragma unroll
        for (int i = 0; i < 4; i++)
#pragma unroll
            for (int j = 0; j < 4; j++)
                Pt[(tx * 4 + j) * APAD + ty * 4 + i] = acc[i][j];
        __syncthreads();

        // O += P V
#pragma unroll 8
        for (int s = 0; s < 64; s++) {
            float4 p4 = *(float4*)&Pt[s * APAD + ty * 4];
            float4 v4 = *(float4*)&Vs[s * APAD + tx * 4];
            float pa[4] = {p4.x, p4.y, p4.z, p4.w};
            float va[4] = {v4.x, v4.y, v4.z, v4.w};
#pragma unroll
            for (int i = 0; i < 4; i++)
#pragma unroll
                for (int j = 0; j < 4; j++)
                    O[i][j] += pa[i] * va[j];
        }
    }

#pragma unroll
    for (int i = 0; i < 4; i++) {
        float inv = 1.0f / lrow[i];
        int t = qt0 + ty * 4 + i;
        float* orow = outp + (b * TT + t) * CC + h * DD + tx * 4;
#pragma unroll
        for (int j = 0; j < 4; j++) orow[j] = O[i][j] * inv;
    }
}

// ---------------------------------------------------------------------------
// Launch
// ---------------------------------------------------------------------------
extern "C" void kernel_launch(void* const* d_in, const int* in_sizes, int n_in,
                              void* d_out, int out_size)
{
    const float* x     = (const float*)d_in[0];
    const void*  pmask = d_in[1];
    const float* Wq    = (const float*)d_in[2];
    const float* Wk    = (const float*)d_in[3];
    const float* Wv    = (const float*)d_in[4];
    const float* Wo    = (const float*)d_in[5];
    const float* bo    = (const float*)d_in[6];
    const float* ln1_g = (const float*)d_in[7];
    const float* ln1_b = (const float*)d_in[8];
    const float* ln2_g = (const float*)d_in[9];
    const float* ln2_b = (const float*)d_in[10];
    const float* W1    = (const float*)d_in[11];
    const float* b1    = (const float*)d_in[12];
    const float* W2    = (const float*)d_in[13];
    const float* b2    = (const float*)d_in[14];
    float* out = (float*)d_out;

    float *p_h, *p_wqkv, *p_qkv, *p_att, *p_proj, *p_h2, *p_ffn1;
    int* p_mask;
    cudaGetSymbolAddress((void**)&p_h,    g_h);
    cudaGetSymbolAddress((void**)&p_wqkv, g_wqkv);
    cudaGetSymbolAddress((void**)&p_qkv,  g_qkv);
    cudaGetSymbolAddress((void**)&p_att,  g_att);
    cudaGetSymbolAddress((void**)&p_proj, g_proj);
    cudaGetSymbolAddress((void**)&p_h2,   g_h2);
    cudaGetSymbolAddress((void**)&p_ffn1, g_ffn1);
    cudaGetSymbolAddress((void**)&p_mask, g_mask);

    // 1. mask classify + expand
    mask_expand_kernel<<<1, 256>>>(pmask, p_mask);

    // 2. pack qkv weights into (C, 3C)
    pack_qkv_kernel<<<(CC * 3 * CC + 255) / 256, 256>>>(Wq, Wk, Wv, p_wqkv);

    // 3. LN1
    ln_kernel<<<MR, 256>>>(x, ln1_g, ln1_b, p_h);

    // 4. QKV projection: (4096x1024) @ (1024x3072)
    sgemm_kernel<<<dim3(3 * CC / 128, MR / 128), 256>>>(p_h, p_wqkv, nullptr, p_qkv,
                                                        MR, 3 * CC, CC, 0);

    // 5. attention
    int attn_smem = 4 * 64 * APAD * (int)sizeof(float);
    cudaFuncSetAttribute(attn_kernel, cudaFuncAttributeMaxDynamicSharedMemorySize, attn_smem);
    attn_kernel<<<dim3(TT / 64, BB * HH), 256, attn_smem>>>(p_qkv, p_mask, p_att);

    // 6. output projection + bias
    sgemm_kernel<<<dim3(CC / 128, MR / 128), 256>>>(p_att, Wo, bo, p_proj,
                                                    MR, CC, CC, 0);

    // 7. LN2
    ln_kernel<<<MR, 256>>>(p_proj, ln2_g, ln2_b, p_h2);

    // 8. FFN1 + relu: (4096x1024) @ (1024x4096)
    sgemm_kernel<<<dim3(FF / 128, MR / 128), 256>>>(p_h2, W1, b1, p_ffn1,
                                                    MR, FF, CC, 1);

    // 9. FFN2: (4096x4096) @ (4096x1024) -> d_out
    sgemm_kernel<<<dim3(CC / 128, MR / 128), 256>>>(p_ffn1, W2, b2, out,
                                                    MR, CC, FF, 0);
}

// round 3
// speedup vs baseline: 1.9304x; 1.9304x over previous
#include <cuda_runtime.h>
#include <cuda_bf16.h>
#include <cstdint>
#include <math.h>

// Problem dims
#define BB 4
#define TT 1024
#define CC 1024
#define HH 16
#define DD 64
#define FF 4096
#define MR 4096   // B*T

// ---------------------------------------------------------------------------
// Scratch (static device globals — no runtime allocation allowed)
// ---------------------------------------------------------------------------
__device__ __align__(256) float g_qkv [MR * 3 * CC];   // q|k|v fp32 (attn input)
__device__ __align__(256) float g_proj[MR * CC];       // Wo projection out
__device__ __align__(256) __nv_bfloat16 g_hH [MR * CC];
__device__ __align__(256) __nv_bfloat16 g_hL [MR * CC];
__device__ __align__(256) __nv_bfloat16 g_atH[MR * CC];
__device__ __align__(256) __nv_bfloat16 g_atL[MR * CC];
__device__ __align__(256) __nv_bfloat16 g_h2H[MR * CC];
__device__ __align__(256) __nv_bfloat16 g_h2L[MR * CC];
__device__ __align__(256) __nv_bfloat16 g_f1H[MR * FF];
__device__ __align__(256) __nv_bfloat16 g_f1L[MR * FF];
__device__ __align__(256) __nv_bfloat16 g_wqH[3 * CC * CC];  // Wqkv^T (3072,1024)
__device__ __align__(256) __nv_bfloat16 g_wqL[3 * CC * CC];
__device__ __align__(256) __nv_bfloat16 g_woH[CC * CC];      // Wo^T
__device__ __align__(256) __nv_bfloat16 g_woL[CC * CC];
__device__ __align__(256) __nv_bfloat16 g_w1H[FF * CC];      // W1^T (4096,1024)
__device__ __align__(256) __nv_bfloat16 g_w1L[FF * CC];
__device__ __align__(256) __nv_bfloat16 g_w2H[CC * FF];      // W2^T (1024,4096)
__device__ __align__(256) __nv_bfloat16 g_w2L[CC * FF];
__device__ int g_mask[MR];

// ---------------------------------------------------------------------------
// Helpers
// ---------------------------------------------------------------------------
__device__ __forceinline__ uint32_t smem_u32(const void* p) {
    uint32_t a;
    asm("{ .reg .u64 t; cvta.to.shared.u64 t, %1; cvt.u32.u64 %0, t; }" : "=r"(a) : "l"(p));
    return a;
}
__device__ __forceinline__ void cp16(uint32_t s, const void* g) {
    asm volatile("cp.async.cg.shared.global [%0], [%1], 16;" :: "r"(s), "l"(g));
}
#define CP_COMMIT() asm volatile("cp.async.commit_group;" ::: "memory")
#define CP_WAIT1()  asm volatile("cp.async.wait_group 1;"  ::: "memory")
#define CP_WAIT0()  asm volatile("cp.async.wait_group 0;"  ::: "memory")

#define LDSM4(r, addr) \
    asm volatile("ldmatrix.sync.aligned.m8n8.x4.shared.b16 {%0,%1,%2,%3}, [%4];" \
        : "=r"((r)[0]), "=r"((r)[1]), "=r"((r)[2]), "=r"((r)[3]) : "r"(addr))

__device__ __forceinline__ void mma16816(float* c, const uint32_t* a, const uint32_t* b) {
    asm volatile("mma.sync.aligned.m16n8k16.row.col.f32.bf16.bf16.f32 "
        "{%0,%1,%2,%3}, {%4,%5,%6,%7}, {%8,%9}, {%0,%1,%2,%3};"
        : "+f"(c[0]), "+f"(c[1]), "+f"(c[2]), "+f"(c[3])
        : "r"(a[0]), "r"(a[1]), "r"(a[2]), "r"(a[3]), "r"(b[0]), "r"(b[1]));
}

__device__ __forceinline__ void split2(float v, __nv_bfloat16& h, __nv_bfloat16& l) {
    h = __float2bfloat16(v);
    l = __float2bfloat16(v - __bfloat162float(h));
}

// ---------------------------------------------------------------------------
// Mask classify + expand
// ---------------------------------------------------------------------------
__global__ void mask_expand_kernel(const void* __restrict__ pm, int* __restrict__ out)
{
    int tid = threadIdx.x;
    const unsigned* w = (const unsigned*)pm;
    int li = 0, lf = 0;
    for (int i = tid; i < 1024; i += 256) {
        unsigned v = w[i];
        li |= (v > 1u);
        lf |= (v != 0u && v != 0x3F800000u);
    }
    int not_int = __syncthreads_or(li);
    int not_flt = __syncthreads_or(lf);
    int cls = (!not_int) ? 0 : ((!not_flt) ? 1 : 2);
    for (int i = tid; i < MR; i += 256) {
        int m;
        if (cls == 0)      m = (((const int*)pm)[i] != 0);
        else if (cls == 1) m = (((const float*)pm)[i] != 0.0f);
        else               m = (((const unsigned char*)pm)[i] != 0);
        out[i] = m;
    }
}

// ---------------------------------------------------------------------------
// Pack Wq/Wk/Wv (H,C,D) -> transposed split (3C, C) bf16 hi/lo
// ---------------------------------------------------------------------------
__global__ void pack_qkv_kernel(const float* __restrict__ Wq,
                                const float* __restrict__ Wk,
                                const float* __restrict__ Wv,
                                __nv_bfloat16* __restrict__ oh,
                                __nv_bfloat16* __restrict__ ol)
{
    int idx = blockIdx.x * blockDim.x + threadIdx.x;
    if (idx >= 3 * CC * CC) return;
    int j = idx / CC;
    int c = idx % CC;
    const float* W = (j < CC) ? Wq : (j < 2 * CC) ? Wk : Wv;
    int jj = j & (CC - 1);
    int h = jj >> 6, d = jj & 63;
    float v = W[(h * CC + c) * DD + d];
    __nv_bfloat16 hh, ll; split2(v, hh, ll);
    oh[idx] = hh; ol[idx] = ll;
}

// ---------------------------------------------------------------------------
// Tiled transpose + split: in (R, Cn) fp32 -> out (Cn, R) bf16 hi/lo
// ---------------------------------------------------------------------------
__global__ void tsplit_kernel(const float* __restrict__ in,
                              __nv_bfloat16* __restrict__ oh,
                              __nv_bfloat16* __restrict__ ol,
                              int R, int Cn)
{
    __shared__ float t[32][33];
    int c0 = blockIdx.x * 32, r0 = blockIdx.y * 32;
    int x = threadIdx.x, y = threadIdx.y;   // 32x8
#pragma unroll
    for (int i = 0; i < 32; i += 8)
        t[y + i][x] = in[(size_t)(r0 + y + i) * Cn + c0 + x];
    __syncthreads();
#pragma unroll
    for (int i = 0; i < 32; i += 8) {
        float v = t[x][y + i];
        __nv_bfloat16 h, l; split2(v, h, l);
        size_t o = (size_t)(c0 + y + i) * R + r0 + x;
        oh[o] = h; ol[o] = l;
    }
}

// ---------------------------------------------------------------------------
// LayerNorm + split
// ---------------------------------------------------------------------------
__global__ __launch_bounds__(256) void ln_split_kernel(const float* __restrict__ x,
                                                       const float* __restrict__ g,
                                                       const float* __restrict__ b,
                                                       __nv_bfloat16* __restrict__ oh,
                                                       __nv_bfloat16* __restrict__ ol)
{
    int row = blockIdx.x, tid = threadIdx.x;
    const float* xr = x + (size_t)row * CC;
    float v[4];
    float s = 0.f, ss = 0.f;
#pragma unroll
    for (int i = 0; i < 4; i++) {
        v[i] = xr[tid + i * 256];
        s += v[i];
        ss += v[i] * v[i];
    }
#pragma unroll
    for (int o = 16; o; o >>= 1) {
        s  += __shfl_xor_sync(0xffffffffu, s,  o);
        ss += __shfl_xor_sync(0xffffffffu, ss, o);
    }
    __shared__ float ws[8], wss[8];
    __shared__ float s_m, s_r;
    int wid = tid >> 5;
    if ((tid & 31) == 0) { ws[wid] = s; wss[wid] = ss; }
    __syncthreads();
    if (tid == 0) {
        float S = 0.f, SS = 0.f;
        for (int i = 0; i < 8; i++) { S += ws[i]; SS += wss[i]; }
        float m = S * (1.0f / CC);
        float var = SS * (1.0f / CC) - m * m;
        s_m = m;
        s_r = rsqrtf(var + 1e-5f);
    }
    __syncthreads();
    float m = s_m, r = s_r;
#pragma unroll
    for (int i = 0; i < 4; i++) {
        int c = tid + i * 256;
        float o = (v[i] - m) * r * g[c] + b[c];
        __nv_bfloat16 hh, ll; split2(o, hh, ll);
        size_t idx = (size_t)row * CC + c;
        oh[idx] = hh; ol[idx] = ll;
    }
}

// ---------------------------------------------------------------------------
// mma.sync bf16 GEMM: D(M,N) = A(M,K) @ B^T, B stored (N,K); split hi/lo
// operands, 3 passes per K-chunk (AhBh + AlBh + AhBl), fp32 accumulate.
// CTA 128x128, K-chunk 64, 8 warps (warp tile 64x32), cp.async double buffer.
// ---------------------------------------------------------------------------
#define PITCH 72                          // padded row (bf16 elems)
#define TILE_B (128 * PITCH * 2)          // one tile bytes (18432)
#define STAGE_B (4 * TILE_B)              // Ah|Al|Bh|Bl   (73728)
#define GEMM_SMEM (2 * STAGE_B)           // double buffer (147456)

__global__ __launch_bounds__(256, 1) void gemm_mma(
    const __nv_bfloat16* __restrict__ Ah, const __nv_bfloat16* __restrict__ Al,
    const __nv_bfloat16* __restrict__ Bh, const __nv_bfloat16* __restrict__ Bl,
    const float* __restrict__ bias,
    float* __restrict__ outF,
    __nv_bfloat16* __restrict__ outH, __nv_bfloat16* __restrict__ outL,
    int Ntot, int Ktot, int relu)
{
    extern __shared__ __align__(128) char smem[];
    const uint32_t sb0 = smem_u32(smem);
    int tid = threadIdx.x, lane = tid & 31, w = tid >> 5;
    int bm = blockIdx.y * 128, bn = blockIdx.x * 128;
    int wm = (w & 1) * 64, wn = (w >> 1) * 32;
    int nk = Ktot >> 6;

    // per-thread cp.async assignment: 4 chunks per tile
    int q_r[4], q_c[4];
#pragma unroll
    for (int i = 0; i < 4; i++) {
        int q = tid + i * 256;
        q_r[i] = q >> 3;
        q_c[i] = (q & 7) * 8;
    }

    float acc[4][4][4] = {};

    // ---- stage loader ----
    auto load_stage = [&](int st, int kc) {
        uint32_t sb = sb0 + st * STAGE_B;
#pragma unroll
        for (int i = 0; i < 4; i++) {
            int r = q_r[i], c = q_c[i];
            uint32_t so = (uint32_t)(r * PITCH + c) * 2;
            size_t goA = (size_t)(bm + r) * Ktot + kc + c;
            size_t goB = (size_t)(bn + r) * Ktot + kc + c;
            cp16(sb + so,              Ah + goA);
            cp16(sb + TILE_B + so,     Al + goA);
            cp16(sb + 2 * TILE_B + so, Bh + goB);
            cp16(sb + 3 * TILE_B + so, Bl + goB);
        }
    };

    load_stage(0, 0);
    CP_COMMIT();

    int lrow = lane & 15;
    int lk = (lane >> 4) * 8;

    for (int kc = 0; kc < nk; kc++) {
        if (kc + 1 < nk) {
            load_stage((kc + 1) & 1, (kc + 1) * 64);
            CP_COMMIT();
            CP_WAIT1();
        } else {
            CP_WAIT0();
        }
        __syncthreads();

        uint32_t sb = sb0 + (kc & 1) * STAGE_B;
#pragma unroll
        for (int ks = 0; ks < 4; ks++) {
            int k0 = ks * 16;
            uint32_t ah[4][4], al[4][4], bh[4][2], bl[4][2];
#pragma unroll
            for (int i = 0; i < 4; i++) {
                uint32_t ad = sb + (uint32_t)((wm + i * 16 + lrow) * PITCH + k0 + lk) * 2;
                LDSM4(ah[i], ad);
                LDSM4(al[i], ad + TILE_B);
            }
#pragma unroll
            for (int jj = 0; jj < 2; jj++) {
                uint32_t bd = sb + 2 * TILE_B +
                              (uint32_t)((wn + jj * 16 + lrow) * PITCH + k0 + lk) * 2;
                uint32_t t[4];
                LDSM4(t, bd);
                bh[jj * 2][0] = t[0]; bh[jj * 2][1] = t[2];
                bh[jj * 2 + 1][0] = t[1]; bh[jj * 2 + 1][1] = t[3];
                LDSM4(t, bd + TILE_B);
                bl[jj * 2][0] = t[0]; bl[jj * 2][1] = t[2];
                bl[jj * 2 + 1][0] = t[1]; bl[jj * 2 + 1][1] = t[3];
            }
#pragma unroll
            for (int i = 0; i < 4; i++)
#pragma unroll
                for (int j = 0; j < 4; j++)
                    mma16816(acc[i][j], ah[i], bh[j]);
#pragma unroll
            for (int i = 0; i < 4; i++)
#pragma unroll
                for (int j = 0; j < 4; j++)
                    mma16816(acc[i][j], al[i], bh[j]);
#pragma unroll
            for (int i = 0; i < 4; i++)
#pragma unroll
                for (int j = 0; j < 4; j++)
                    mma16816(acc[i][j], ah[i], bl[j]);
        }
        __syncthreads();
    }

    // ---- epilogue ----
#pragma unroll
    for (int i = 0; i < 4; i++) {
        int r0 = bm + wm + i * 16 + (lane >> 2);
#pragma unroll
        for (int j = 0; j < 4; j++) {
            int c = bn + wn + j * 8 + (lane & 3) * 2;
            float bx0 = bias ? bias[c] : 0.0f;
            float bx1 = bias ? bias[c + 1] : 0.0f;
#pragma unroll
            for (int hh = 0; hh < 2; hh++) {
                int r = r0 + hh * 8;
                float v0 = acc[i][j][hh * 2 + 0] + bx0;
                float v1 = acc[i][j][hh * 2 + 1] + bx1;
                if (relu) { v0 = fmaxf(v0, 0.0f); v1 = fmaxf(v1, 0.0f); }
                size_t o = (size_t)r * Ntot + c;
                if (outF) {
                    outF[o] = v0;
                    outF[o + 1] = v1;
                } else {
                    __nv_bfloat16 h0, l0, h1, l1;
                    split2(v0, h0, l0);
                    split2(v1, h1, l1);
                    __nv_bfloat162 hp; hp.x = h0; hp.y = h1;
                    __nv_bfloat162 lp; lp.x = l0; lp.y = l1;
                    *(__nv_bfloat162*)(outH + o) = hp;
                    *(__nv_bfloat162*)(outL + o) = lp;
                }
            }
        }
    }
}

// ---------------------------------------------------------------------------
// Attention (fp32 SIMT flash, FULL sequence sweep — padding applied after
// causal makes future padded columns finite, so they cannot be skipped).
// Epilogue writes split bf16 hi/lo for the Wo GEMM.
// ---------------------------------------------------------------------------
#define APAD 68
__global__ __launch_bounds__(256) void attn_kernel(const float* __restrict__ qkv,
                                                   const int* __restrict__ mask,
                                                   __nv_bfloat16* __restrict__ outH,
                                                   __nv_bfloat16* __restrict__ outL)
{
    extern __shared__ __align__(16) float sm[];
    float* Qt = sm;
    float* Kt = sm + 64 * APAD;
    float* Vs = sm + 2 * 64 * APAD;
    float* Pt = sm + 3 * 64 * APAD;

    int bh = blockIdx.y;
    int b = bh >> 4, h = bh & 15;
    int qt0 = blockIdx.x * 64;
    int tid = threadIdx.x;
    int ty = tid >> 4, tx = tid & 15;

    const float* base = qkv + (size_t)(b * TT) * (3 * CC) + h * DD;

    for (int i = tid; i < 4096; i += 256) {
        int r = i >> 6, d = i & 63;
        Qt[d * APAD + r] = base[(size_t)(qt0 + r) * (3 * CC) + d];
    }

    float mrow[4], lrow[4], O[4][4];
#pragma unroll
    for (int i = 0; i < 4; i++) {
        mrow[i] = -INFINITY;
        lrow[i] = 0.0f;
#pragma unroll
        for (int j = 0; j < 4; j++) O[i][j] = 0.0f;
    }
    const int* mrowp = mask + b * TT;

    for (int st0 = 0; st0 < TT; st0 += 64) {
        __syncthreads();
        for (int i = tid; i < 4096; i += 256) {
            int r = i >> 6, d = i & 63;
            Kt[d * APAD + r] = base[(size_t)(st0 + r) * (3 * CC) + CC + d];
            Vs[r * APAD + d] = base[(size_t)(st0 + r) * (3 * CC) + 2 * CC + d];
        }
        __syncthreads();

        float acc[4][4] = {};
#pragma unroll 8
        for (int d = 0; d < 64; d++) {
            float4 q4 = *(float4*)&Qt[d * APAD + ty * 4];
            float4 k4 = *(float4*)&Kt[d * APAD + tx * 4];
            float qa[4] = {q4.x, q4.y, q4.z, q4.w};
            float ka[4] = {k4.x, k4.y, k4.z, k4.w};
#pragma unroll
            for (int i = 0; i < 4; i++)
#pragma unroll
                for (int j = 0; j < 4; j++)
                    acc[i][j] += qa[i] * ka[j];
        }

#pragma unroll
        for (int i = 0; i < 4; i++) {
            int t = qt0 + ty * 4 + i;
#pragma unroll
            for (int j = 0; j < 4; j++) {
                int s = st0 + tx * 4 + j;
                float v = acc[i][j] * 0.03125f;
                if (s > t) v = -INFINITY;
                if (mrowp[s]) v = -1e9f;
                acc[i][j] = v;
            }
        }

#pragma unroll
        for (int i = 0; i < 4; i++) {
            float mt = fmaxf(fmaxf(acc[i][0], acc[i][1]), fmaxf(acc[i][2], acc[i][3]));
            mt = fmaxf(mt, __shfl_xor_sync(0xffffffffu, mt, 1));
            mt = fmaxf(mt, __shfl_xor_sync(0xffffffffu, mt, 2));
            mt = fmaxf(mt, __shfl_xor_sync(0xffffffffu, mt, 4));
            mt = fmaxf(mt, __shfl_xor_sync(0xffffffffu, mt, 8));
            float mn = fmaxf(mrow[i], mt);
            float f = __expf(mrow[i] - mn);
            float ps = 0.0f;
#pragma unroll
            for (int j = 0; j < 4; j++) {
                float p = __expf(acc[i][j] - mn);
                acc[i][j] = p;
                ps += p;
            }
            ps += __shfl_xor_sync(0xffffffffu, ps, 1);
            ps += __shfl_xor_sync(0xffffffffu, ps, 2);
            ps += __shfl_xor_sync(0xffffffffu, ps, 4);
            ps += __shfl_xor_sync(0xffffffffu, ps, 8);
            lrow[i] = lrow[i] * f + ps;
            mrow[i] = mn;
#pragma unroll
            for (int j = 0; j < 4; j++) O[i][j] *= f;
        }

#pragma unroll
        for (int i = 0; i < 4; i++)
#pragma unroll
            for (int j = 0; j < 4; j++)
                Pt[(tx * 4 + j) * APAD + ty * 4 + i] = acc[i][j];
        __syncthreads();

#pragma unroll 8
        for (int s = 0; s < 64; s++) {
            float4 p4 = *(float4*)&Pt[s * APAD + ty * 4];
            float4 v4 = *(float4*)&Vs[s * APAD + tx * 4];
            float pa[4] = {p4.x, p4.y, p4.z, p4.w};
            float va[4] = {v4.x, v4.y, v4.z, v4.w};
#pragma unroll
            for (int i = 0; i < 4; i++)
#pragma unroll
                for (int j = 0; j < 4; j++)
                    O[i][j] += pa[i] * va[j];
        }
    }

#pragma unroll
    for (int i = 0; i < 4; i++) {
        float inv = 1.0f / lrow[i];
        int t = qt0 + ty * 4 + i;
        size_t o = (size_t)(b * TT + t) * CC + h * DD + tx * 4;
#pragma unroll
        for (int j = 0; j < 4; j += 2) {
            __nv_bfloat16 h0, l0, h1, l1;
            split2(O[i][j] * inv, h0, l0);
            split2(O[i][j + 1] * inv, h1, l1);
            __nv_bfloat162 hp; hp.x = h0; hp.y = h1;
            __nv_bfloat162 lp; lp.x = l0; lp.y = l1;
            *(__nv_bfloat162*)(outH + o + j) = hp;
            *(__nv_bfloat162*)(outL + o + j) = lp;
        }
    }
}

// ---------------------------------------------------------------------------
// Launch
// ---------------------------------------------------------------------------
extern "C" void kernel_launch(void* const* d_in, const int* in_sizes, int n_in,
                              void* d_out, int out_size)
{
    const float* x     = (const float*)d_in[0];
    const void*  pmask = d_in[1];
    const float* Wq    = (const float*)d_in[2];
    const float* Wk    = (const float*)d_in[3];
    const float* Wv    = (const float*)d_in[4];
    const float* Wo    = (const float*)d_in[5];
    const float* bo    = (const float*)d_in[6];
    const float* ln1_g = (const float*)d_in[7];
    const float* ln1_b = (const float*)d_in[8];
    const float* ln2_g = (const float*)d_in[9];
    const float* ln2_b = (const float*)d_in[10];
    const float* W1    = (const float*)d_in[11];
    const float* b1    = (const float*)d_in[12];
    const float* W2    = (const float*)d_in[13];
    const float* b2    = (const float*)d_in[14];
    float* out = (float*)d_out;

    void *p_qkv, *p_proj, *p_hH, *p_hL, *p_atH, *p_atL, *p_h2H, *p_h2L,
         *p_f1H, *p_f1L, *p_wqH, *p_wqL, *p_woH, *p_woL, *p_w1H, *p_w1L,
         *p_w2H, *p_w2L, *p_mask;
    cudaGetSymbolAddress(&p_qkv,  g_qkv);
    cudaGetSymbolAddress(&p_proj, g_proj);
    cudaGetSymbolAddress(&p_hH,   g_hH);
    cudaGetSymbolAddress(&p_hL,   g_hL);
    cudaGetSymbolAddress(&p_atH,  g_atH);
    cudaGetSymbolAddress(&p_atL,  g_atL);
    cudaGetSymbolAddress(&p_h2H,  g_h2H);
    cudaGetSymbolAddress(&p_h2L,  g_h2L);
    cudaGetSymbolAddress(&p_f1H,  g_f1H);
    cudaGetSymbolAddress(&p_f1L,  g_f1L);
    cudaGetSymbolAddress(&p_wqH,  g_wqH);
    cudaGetSymbolAddress(&p_wqL,  g_wqL);
    cudaGetSymbolAddress(&p_woH,  g_woH);
    cudaGetSymbolAddress(&p_woL,  g_woL);
    cudaGetSymbolAddress(&p_w1H,  g_w1H);
    cudaGetSymbolAddress(&p_w1L,  g_w1L);
    cudaGetSymbolAddress(&p_w2H,  g_w2H);
    cudaGetSymbolAddress(&p_w2L,  g_w2L);
    cudaGetSymbolAddress(&p_mask, g_mask);

    cudaFuncSetAttribute(gemm_mma, cudaFuncAttributeMaxDynamicSharedMemorySize, GEMM_SMEM);
    int attn_smem = 4 * 64 * APAD * (int)sizeof(float);
    cudaFuncSetAttribute(attn_kernel, cudaFuncAttributeMaxDynamicSharedMemorySize, attn_smem);

    // 1. mask
    mask_expand_kernel<<<1, 256>>>(pmask, (int*)p_mask);
    // 2. weight prep (transpose + split)
    pack_qkv_kernel<<<(3 * CC * CC + 255) / 256, 256>>>(
        Wq, Wk, Wv, (__nv_bfloat16*)p_wqH, (__nv_bfloat16*)p_wqL);
    tsplit_kernel<<<dim3(CC / 32, CC / 32), dim3(32, 8)>>>(
        Wo, (__nv_bfloat16*)p_woH, (__nv_bfloat16*)p_woL, CC, CC);
    tsplit_kernel<<<dim3(FF / 32, CC / 32), dim3(32, 8)>>>(
        W1, (__nv_bfloat16*)p_w1H, (__nv_bfloat16*)p_w1L, CC, FF);
    tsplit_kernel<<<dim3(CC / 32, FF / 32), dim3(32, 8)>>>(
        W2, (__nv_bfloat16*)p_w2H, (__nv_bfloat16*)p_w2L, FF, CC);
    // 3. LN1
    ln_split_kernel<<<MR, 256>>>(x, ln1_g, ln1_b,
                                 (__nv_bfloat16*)p_hH, (__nv_bfloat16*)p_hL);
    // 4. QKV gemm -> fp32 qkv
    gemm_mma<<<dim3(3 * CC / 128, MR / 128), 256, GEMM_SMEM>>>(
        (__nv_bfloat16*)p_hH, (__nv_bfloat16*)p_hL,
        (__nv_bfloat16*)p_wqH, (__nv_bfloat16*)p_wqL, nullptr,
        (float*)p_qkv, nullptr, nullptr, 3 * CC, CC, 0);
    // 5. attention -> split att
    attn_kernel<<<dim3(TT / 64, BB * HH), 256, attn_smem>>>(
        (const float*)p_qkv, (const int*)p_mask,
        (__nv_bfloat16*)p_atH, (__nv_bfloat16*)p_atL);
    // 6. Wo projection + bias -> fp32 proj
    gemm_mma<<<dim3(CC / 128, MR / 128), 256, GEMM_SMEM>>>(
        (__nv_bfloat16*)p_atH, (__nv_bfloat16*)p_atL,
        (__nv_bfloat16*)p_woH, (__nv_bfloat16*)p_woL, bo,
        (float*)p_proj, nullptr, nullptr, CC, CC, 0);
    // 7. LN2
    ln_split_kernel<<<MR, 256>>>((const float*)p_proj, ln2_g, ln2_b,
                                 (__nv_bfloat16*)p_h2H, (__nv_bfloat16*)p_h2L);
    // 8. FFN1 + bias + relu -> split f1
    gemm_mma<<<dim3(FF / 128, MR / 128), 256, GEMM_SMEM>>>(
        (__nv_bfloat16*)p_h2H, (__nv_bfloat16*)p_h2L,
        (__nv_bfloat16*)p_w1H, (__nv_bfloat16*)p_w1L, b1,
        nullptr, (__nv_bfloat16*)p_f1H, (__nv_bfloat16*)p_f1L, FF, CC, 1);
    // 9. FFN2 + bias -> d_out
    gemm_mma<<<dim3(CC / 128, MR / 128), 256, GEMM_SMEM>>>(
        (__nv_bfloat16*)p_f1H, (__nv_bfloat16*)p_f1L,
        (__nv_bfloat16*)p_w2H, (__nv_bfloat16*)p_w2L, b2,
        out, nullptr, nullptr, CC, FF, 0);
}

// round 4
// speedup vs baseline: 2.1728x; 1.1256x over previous
#include <cuda_runtime.h>
#include <cuda_bf16.h>
#include <cstdint>
#include <math.h>

// Problem dims
#define BB 4
#define TT 1024
#define CC 1024
#define HH 16
#define DD 64
#define FF 4096
#define MR 4096   // B*T

// ---------------------------------------------------------------------------
// Scratch (static device globals)
// ---------------------------------------------------------------------------
__device__ __align__(256) float g_proj[MR * CC];             // Wo out (LN2 input)
__device__ __align__(256) __nv_bfloat16 g_qkvH[MR * 3 * CC]; // qkv split hi/lo
__device__ __align__(256) __nv_bfloat16 g_qkvL[MR * 3 * CC];
__device__ __align__(256) __nv_bfloat16 g_hH [MR * CC];
__device__ __align__(256) __nv_bfloat16 g_hL [MR * CC];
__device__ __align__(256) __nv_bfloat16 g_atH[MR * CC];
__device__ __align__(256) __nv_bfloat16 g_atL[MR * CC];
__device__ __align__(256) __nv_bfloat16 g_h2H[MR * CC];
__device__ __align__(256) __nv_bfloat16 g_h2L[MR * CC];
__device__ __align__(256) __nv_bfloat16 g_f1H[MR * FF];
__device__ __align__(256) __nv_bfloat16 g_f1L[MR * FF];
__device__ __align__(256) __nv_bfloat16 g_wqH[3 * CC * CC];
__device__ __align__(256) __nv_bfloat16 g_wqL[3 * CC * CC];
__device__ __align__(256) __nv_bfloat16 g_woH[CC * CC];
__device__ __align__(256) __nv_bfloat16 g_woL[CC * CC];
__device__ __align__(256) __nv_bfloat16 g_w1H[FF * CC];
__device__ __align__(256) __nv_bfloat16 g_w1L[FF * CC];
__device__ __align__(256) __nv_bfloat16 g_w2H[CC * FF];
__device__ __align__(256) __nv_bfloat16 g_w2L[CC * FF];
__device__ int g_mask[MR];
__device__ int g_fu[BB];    // first unpadded index per batch

// ---------------------------------------------------------------------------
// Helpers
// ---------------------------------------------------------------------------
__device__ __forceinline__ uint32_t smem_u32(const void* p) {
    uint32_t a;
    asm("{ .reg .u64 t; cvta.to.shared.u64 t, %1; cvt.u32.u64 %0, t; }" : "=r"(a) : "l"(p));
    return a;
}
__device__ __forceinline__ void cp16(uint32_t s, const void* g) {
    asm volatile("cp.async.cg.shared.global [%0], [%1], 16;" :: "r"(s), "l"(g));
}
#define CP_COMMIT() asm volatile("cp.async.commit_group;" ::: "memory")
#define CP_WAIT1()  asm volatile("cp.async.wait_group 1;"  ::: "memory")
#define CP_WAIT0()  asm volatile("cp.async.wait_group 0;"  ::: "memory")

#define LDSM4(r, addr) \
    asm volatile("ldmatrix.sync.aligned.m8n8.x4.shared.b16 {%0,%1,%2,%3}, [%4];" \
        : "=r"((r)[0]), "=r"((r)[1]), "=r"((r)[2]), "=r"((r)[3]) : "r"(addr))
#define LDSM4T(r, addr) \
    asm volatile("ldmatrix.sync.aligned.m8n8.x4.trans.shared.b16 {%0,%1,%2,%3}, [%4];" \
        : "=r"((r)[0]), "=r"((r)[1]), "=r"((r)[2]), "=r"((r)[3]) : "r"(addr))

__device__ __forceinline__ void mma16816(float* c, const uint32_t* a, const uint32_t* b) {
    asm volatile("mma.sync.aligned.m16n8k16.row.col.f32.bf16.bf16.f32 "
        "{%0,%1,%2,%3}, {%4,%5,%6,%7}, {%8,%9}, {%0,%1,%2,%3};"
        : "+f"(c[0]), "+f"(c[1]), "+f"(c[2]), "+f"(c[3])
        : "r"(a[0]), "r"(a[1]), "r"(a[2]), "r"(a[3]), "r"(b[0]), "r"(b[1]));
}

__device__ __forceinline__ void split2(float v, __nv_bfloat16& h, __nv_bfloat16& l) {
    h = __float2bfloat16(v);
    l = __float2bfloat16(v - __bfloat162float(h));
}
__device__ __forceinline__ float fex2(float x) {
    float r;
    asm("ex2.approx.ftz.f32 %0, %1;" : "=f"(r) : "f"(x));
    return r;
}

// ---------------------------------------------------------------------------
// Mask classify + expand + first-unpadded per batch
// ---------------------------------------------------------------------------
__global__ void mask_expand_kernel(const void* __restrict__ pm, int* __restrict__ out)
{
    int tid = threadIdx.x;
    if (tid < BB) g_fu[tid] = TT;
    const unsigned* w = (const unsigned*)pm;
    int li = 0, lf = 0;
    for (int i = tid; i < 1024; i += 256) {
        unsigned v = w[i];
        li |= (v > 1u);
        lf |= (v != 0u && v != 0x3F800000u);
    }
    int not_int = __syncthreads_or(li);
    int not_flt = __syncthreads_or(lf);
    int cls = (!not_int) ? 0 : ((!not_flt) ? 1 : 2);
    for (int i = tid; i < MR; i += 256) {
        int m;
        if (cls == 0)      m = (((const int*)pm)[i] != 0);
        else if (cls == 1) m = (((const float*)pm)[i] != 0.0f);
        else               m = (((const unsigned char*)pm)[i] != 0);
        out[i] = m;
        if (!m) atomicMin(&g_fu[i >> 10], i & 1023);
    }
}

// ---------------------------------------------------------------------------
// Pack Wq/Wk/Wv (H,C,D) -> transposed split (3C, C) bf16 hi/lo
// ---------------------------------------------------------------------------
__global__ void pack_qkv_kernel(const float* __restrict__ Wq,
                                const float* __restrict__ Wk,
                                const float* __restrict__ Wv,
                                __nv_bfloat16* __restrict__ oh,
                                __nv_bfloat16* __restrict__ ol)
{
    int idx = blockIdx.x * blockDim.x + threadIdx.x;
    if (idx >= 3 * CC * CC) return;
    int j = idx / CC;
    int c = idx % CC;
    const float* W = (j < CC) ? Wq : (j < 2 * CC) ? Wk : Wv;
    int jj = j & (CC - 1);
    int h = jj >> 6, d = jj & 63;
    float v = W[(h * CC + c) * DD + d];
    __nv_bfloat16 hh, ll; split2(v, hh, ll);
    oh[idx] = hh; ol[idx] = ll;
}

// ---------------------------------------------------------------------------
// Tiled transpose + split
// ---------------------------------------------------------------------------
__global__ void tsplit_kernel(const float* __restrict__ in,
                              __nv_bfloat16* __restrict__ oh,
                              __nv_bfloat16* __restrict__ ol,
                              int R, int Cn)
{
    __shared__ float t[32][33];
    int c0 = blockIdx.x * 32, r0 = blockIdx.y * 32;
    int x = threadIdx.x, y = threadIdx.y;
#pragma unroll
    for (int i = 0; i < 32; i += 8)
        t[y + i][x] = in[(size_t)(r0 + y + i) * Cn + c0 + x];
    __syncthreads();
#pragma unroll
    for (int i = 0; i < 32; i += 8) {
        float v = t[x][y + i];
        __nv_bfloat16 h, l; split2(v, h, l);
        size_t o = (size_t)(c0 + y + i) * R + r0 + x;
        oh[o] = h; ol[o] = l;
    }
}

// ---------------------------------------------------------------------------
// LayerNorm + split
// ---------------------------------------------------------------------------
__global__ __launch_bounds__(256) void ln_split_kernel(const float* __restrict__ x,
                                                       const float* __restrict__ g,
                                                       const float* __restrict__ b,
                                                       __nv_bfloat16* __restrict__ oh,
                                                       __nv_bfloat16* __restrict__ ol)
{
    int row = blockIdx.x, tid = threadIdx.x;
    const float* xr = x + (size_t)row * CC;
    float v[4];
    float s = 0.f, ss = 0.f;
#pragma unroll
    for (int i = 0; i < 4; i++) {
        v[i] = xr[tid + i * 256];
        s += v[i];
        ss += v[i] * v[i];
    }
#pragma unroll
    for (int o = 16; o; o >>= 1) {
        s  += __shfl_xor_sync(0xffffffffu, s,  o);
        ss += __shfl_xor_sync(0xffffffffu, ss, o);
    }
    __shared__ float ws[8], wss[8];
    __shared__ float s_m, s_r;
    int wid = tid >> 5;
    if ((tid & 31) == 0) { ws[wid] = s; wss[wid] = ss; }
    __syncthreads();
    if (tid == 0) {
        float S = 0.f, SS = 0.f;
        for (int i = 0; i < 8; i++) { S += ws[i]; SS += wss[i]; }
        float m = S * (1.0f / CC);
        float var = SS * (1.0f / CC) - m * m;
        s_m = m;
        s_r = rsqrtf(var + 1e-5f);
    }
    __syncthreads();
    float m = s_m, r = s_r;
#pragma unroll
    for (int i = 0; i < 4; i++) {
        int c = tid + i * 256;
        float o = (v[i] - m) * r * g[c] + b[c];
        __nv_bfloat16 hh, ll; split2(o, hh, ll);
        size_t idx = (size_t)row * CC + c;
        oh[idx] = hh; ol[idx] = ll;
    }
}

// ---------------------------------------------------------------------------
// mma.sync bf16 GEMM (unchanged from R3)
// ---------------------------------------------------------------------------
#define PITCH 72
#define TILE_B (128 * PITCH * 2)
#define STAGE_B (4 * TILE_B)
#define GEMM_SMEM (2 * STAGE_B)

__global__ __launch_bounds__(256, 1) void gemm_mma(
    const __nv_bfloat16* __restrict__ Ah, const __nv_bfloat16* __restrict__ Al,
    const __nv_bfloat16* __restrict__ Bh, const __nv_bfloat16* __restrict__ Bl,
    const float* __restrict__ bias,
    float* __restrict__ outF,
    __nv_bfloat16* __restrict__ outH, __nv_bfloat16* __restrict__ outL,
    int Ntot, int Ktot, int relu)
{
    extern __shared__ __align__(128) char smem[];
    const uint32_t sb0 = smem_u32(smem);
    int tid = threadIdx.x, lane = tid & 31, w = tid >> 5;
    int bm = blockIdx.y * 128, bn = blockIdx.x * 128;
    int wm = (w & 1) * 64, wn = (w >> 1) * 32;
    int nk = Ktot >> 6;

    int q_r[4], q_c[4];
#pragma unroll
    for (int i = 0; i < 4; i++) {
        int q = tid + i * 256;
        q_r[i] = q >> 3;
        q_c[i] = (q & 7) * 8;
    }

    float acc[4][4][4] = {};

    auto load_stage = [&](int st, int kc) {
        uint32_t sb = sb0 + st * STAGE_B;
#pragma unroll
        for (int i = 0; i < 4; i++) {
            int r = q_r[i], c = q_c[i];
            uint32_t so = (uint32_t)(r * PITCH + c) * 2;
            size_t goA = (size_t)(bm + r) * Ktot + kc + c;
            size_t goB = (size_t)(bn + r) * Ktot + kc + c;
            cp16(sb + so,              Ah + goA);
            cp16(sb + TILE_B + so,     Al + goA);
            cp16(sb + 2 * TILE_B + so, Bh + goB);
            cp16(sb + 3 * TILE_B + so, Bl + goB);
        }
    };

    load_stage(0, 0);
    CP_COMMIT();

    int lrow = lane & 15;
    int lk = (lane >> 4) * 8;

    for (int kc = 0; kc < nk; kc++) {
        if (kc + 1 < nk) {
            load_stage((kc + 1) & 1, (kc + 1) * 64);
            CP_COMMIT();
            CP_WAIT1();
        } else {
            CP_WAIT0();
        }
        __syncthreads();

        uint32_t sb = sb0 + (kc & 1) * STAGE_B;
#pragma unroll
        for (int ks = 0; ks < 4; ks++) {
            int k0 = ks * 16;
            uint32_t ah[4][4], al[4][4], bh[4][2], bl[4][2];
#pragma unroll
            for (int i = 0; i < 4; i++) {
                uint32_t ad = sb + (uint32_t)((wm + i * 16 + lrow) * PITCH + k0 + lk) * 2;
                LDSM4(ah[i], ad);
                LDSM4(al[i], ad + TILE_B);
            }
#pragma unroll
            for (int jj = 0; jj < 2; jj++) {
                uint32_t bd = sb + 2 * TILE_B +
                              (uint32_t)((wn + jj * 16 + lrow) * PITCH + k0 + lk) * 2;
                uint32_t t[4];
                LDSM4(t, bd);
                bh[jj * 2][0] = t[0]; bh[jj * 2][1] = t[2];
                bh[jj * 2 + 1][0] = t[1]; bh[jj * 2 + 1][1] = t[3];
                LDSM4(t, bd + TILE_B);
                bl[jj * 2][0] = t[0]; bl[jj * 2][1] = t[2];
                bl[jj * 2 + 1][0] = t[1]; bl[jj * 2 + 1][1] = t[3];
            }
#pragma unroll
            for (int i = 0; i < 4; i++)
#pragma unroll
                for (int j = 0; j < 4; j++)
                    mma16816(acc[i][j], ah[i], bh[j]);
#pragma unroll
            for (int i = 0; i < 4; i++)
#pragma unroll
                for (int j = 0; j < 4; j++)
                    mma16816(acc[i][j], al[i], bh[j]);
#pragma unroll
            for (int i = 0; i < 4; i++)
#pragma unroll
                for (int j = 0; j < 4; j++)
                    mma16816(acc[i][j], ah[i], bl[j]);
        }
        __syncthreads();
    }

#pragma unroll
    for (int i = 0; i < 4; i++) {
        int r0 = bm + wm + i * 16 + (lane >> 2);
#pragma unroll
        for (int j = 0; j < 4; j++) {
            int c = bn + wn + j * 8 + (lane & 3) * 2;
            float bx0 = bias ? bias[c] : 0.0f;
            float bx1 = bias ? bias[c + 1] : 0.0f;
#pragma unroll
            for (int hh = 0; hh < 2; hh++) {
                int r = r0 + hh * 8;
                float v0 = acc[i][j][hh * 2 + 0] + bx0;
                float v1 = acc[i][j][hh * 2 + 1] + bx1;
                if (relu) { v0 = fmaxf(v0, 0.0f); v1 = fmaxf(v1, 0.0f); }
                size_t o = (size_t)r * Ntot + c;
                if (outF) {
                    outF[o] = v0;
                    outF[o + 1] = v1;
                } else {
                    __nv_bfloat16 h0, l0, h1, l1;
                    split2(v0, h0, l0);
                    split2(v1, h1, l1);
                    __nv_bfloat162 hp; hp.x = h0; hp.y = h1;
                    __nv_bfloat162 lp; lp.x = l0; lp.y = l1;
                    *(__nv_bfloat162*)(outH + o) = hp;
                    *(__nv_bfloat162*)(outL + o) = lp;
                }
            }
        }
    }
}

// ---------------------------------------------------------------------------
// Tensor-core flash attention, causal-only sweep, no running max.
// CTA: 128 threads (4 warps), 64 q-rows; each warp owns 16 q-rows.
// Padded / causal-masked entries get exponent -1e9 -> ex2 -> exactly 0.
// Degenerate rows (whole causal prefix padded) produce l=0 -> NaN, fixed up
// by fixup_kernel afterwards.
// ---------------------------------------------------------------------------
#define AT_PITCH 72
#define AT_TILEB (64 * AT_PITCH * 2)      // 9216 bytes
#define ATT_SMEM (6 * AT_TILEB + 256)

__global__ __launch_bounds__(128) void attn_mma(
    const __nv_bfloat16* __restrict__ qkvH,
    const __nv_bfloat16* __restrict__ qkvL,
    const int* __restrict__ mask,
    __nv_bfloat16* __restrict__ outH,
    __nv_bfloat16* __restrict__ outL)
{
    extern __shared__ __align__(128) char smem[];
    const uint32_t sb = smem_u32(smem);
    const uint32_t sQh = sb,               sQl = sb + AT_TILEB;
    const uint32_t sKh = sb + 2 * AT_TILEB, sKl = sb + 3 * AT_TILEB;
    const uint32_t sVh = sb + 4 * AT_TILEB, sVl = sb + 5 * AT_TILEB;
    int* smask = (int*)(smem + 6 * AT_TILEB);

    int qi = blockIdx.x;               // q block (16)
    int bh = blockIdx.y;               // b*16 + h
    int b = bh >> 4, h = bh & 15;
    int tid = threadIdx.x, lane = tid & 31, w = tid >> 5;
    int wq = w * 16;
    int lrow = lane & 15, lkc = (lane >> 4) * 8;

    const size_t rowbase = (size_t)(b * TT) * (3 * CC) + h * DD;

    // Q tile load (hi+lo)
#pragma unroll
    for (int i = 0; i < 4; i++) {
        int idx = tid + i * 128;
        int r = idx >> 3, ch = (idx & 7) * 8;
        uint32_t so = (uint32_t)(r * AT_PITCH + ch) * 2;
        size_t go = rowbase + (size_t)(qi * 64 + r) * (3 * CC) + ch;
        cp16(sQh + so, qkvH + go);
        cp16(sQl + so, qkvL + go);
    }
    CP_COMMIT();

    float O[8][4];
#pragma unroll
    for (int j = 0; j < 8; j++)
#pragma unroll
        for (int e = 0; e < 4; e++) O[j][e] = 0.0f;
    float lsum0 = 0.0f, lsum1 = 0.0f;

    const float csc = 0.0450842200f;   // log2(e) / 32

    for (int sj = 0; sj <= qi; sj++) {
        __syncthreads();   // previous compute done with K/V smem
        // K/V tiles (hi+lo)
#pragma unroll
        for (int i = 0; i < 4; i++) {
            int idx = tid + i * 128;
            int r = idx >> 3, ch = (idx & 7) * 8;
            uint32_t so = (uint32_t)(r * AT_PITCH + ch) * 2;
            size_t gk = rowbase + (size_t)(sj * 64 + r) * (3 * CC) + CC + ch;
            size_t gv = gk + CC;
            cp16(sKh + so, qkvH + gk);
            cp16(sKl + so, qkvL + gk);
            cp16(sVh + so, qkvH + gv);
            cp16(sVl + so, qkvL + gv);
        }
        if (tid < 64) smask[tid] = mask[b * TT + sj * 64 + tid];
        CP_COMMIT();
        CP_WAIT0();
        __syncthreads();

        // ---- S = Q K^T (3-pass split) ----
        float S[8][4];
#pragma unroll
        for (int j = 0; j < 8; j++)
#pragma unroll
            for (int e = 0; e < 4; e++) S[j][e] = 0.0f;

#pragma unroll
        for (int ks = 0; ks < 4; ks++) {
            uint32_t qa[4], ql[4];
            uint32_t ad = sQh + (uint32_t)((wq + lrow) * AT_PITCH + ks * 16 + lkc) * 2;
            LDSM4(qa, ad);
            LDSM4(ql, ad + AT_TILEB);
#pragma unroll
            for (int nj = 0; nj < 4; nj++) {
                uint32_t bd = sKh + (uint32_t)((nj * 16 + lrow) * AT_PITCH + ks * 16 + lkc) * 2;
                uint32_t th[4], tl[4];
                LDSM4(th, bd);
                LDSM4(tl, bd + AT_TILEB);
                uint32_t bh0[2] = {th[0], th[2]}, bh1[2] = {th[1], th[3]};
                uint32_t bl0[2] = {tl[0], tl[2]}, bl1[2] = {tl[1], tl[3]};
                mma16816(S[2 * nj],     qa, bh0);
                mma16816(S[2 * nj + 1], qa, bh1);
                mma16816(S[2 * nj],     ql, bh0);
                mma16816(S[2 * nj + 1], ql, bh1);
                mma16816(S[2 * nj],     qa, bl0);
                mma16816(S[2 * nj + 1], qa, bl1);
            }
        }

        // ---- mask + exp2 (no max subtraction) ----
        int t_loc = wq + (lane >> 2);
        bool diag = (sj == qi);
#pragma unroll
        for (int j = 0; j < 8; j++) {
            int s0 = j * 8 + (lane & 3) * 2;
#pragma unroll
            for (int e = 0; e < 4; e++) {
                int s_l = s0 + (e & 1);
                int t_l = t_loc + (e >> 1) * 8;
                float v = S[j][e] * csc;
                if (smask[s_l] || (diag && s_l > t_l)) v = -1e9f;
                float p = fex2(v);
                S[j][e] = p;
            }
            lsum0 += S[j][0] + S[j][1];
            lsum1 += S[j][2] + S[j][3];
        }

        // ---- pack P into A-fragments (hi/lo) ----
        uint32_t aPh[8][2], aPl[8][2];
#pragma unroll
        for (int j = 0; j < 8; j++) {
            __nv_bfloat162 h0 = __floats2bfloat162_rn(S[j][0], S[j][1]);
            __nv_bfloat162 h1 = __floats2bfloat162_rn(S[j][2], S[j][3]);
            float r00 = S[j][0] - __bfloat162float(h0.x);
            float r01 = S[j][1] - __bfloat162float(h0.y);
            float r10 = S[j][2] - __bfloat162float(h1.x);
            float r11 = S[j][3] - __bfloat162float(h1.y);
            __nv_bfloat162 l0 = __floats2bfloat162_rn(r00, r01);
            __nv_bfloat162 l1 = __floats2bfloat162_rn(r10, r11);
            aPh[j][0] = *(uint32_t*)&h0; aPh[j][1] = *(uint32_t*)&h1;
            aPl[j][0] = *(uint32_t*)&l0; aPl[j][1] = *(uint32_t*)&l1;
        }

        // ---- O += P V (3-pass split), V via ldmatrix.trans ----
#pragma unroll
        for (int kc = 0; kc < 4; kc++) {
            uint32_t Ah[4] = {aPh[2 * kc][0], aPh[2 * kc][1],
                              aPh[2 * kc + 1][0], aPh[2 * kc + 1][1]};
            uint32_t Al[4] = {aPl[2 * kc][0], aPl[2 * kc][1],
                              aPl[2 * kc + 1][0], aPl[2 * kc + 1][1]};
#pragma unroll
            for (int dj = 0; dj < 4; dj++) {
                uint32_t vd = sVh + (uint32_t)((kc * 16 + lrow) * AT_PITCH + dj * 16 + lkc) * 2;
                uint32_t tvh[4], tvl[4];
                LDSM4T(tvh, vd);
                LDSM4T(tvl, vd + AT_TILEB);
                uint32_t bh0[2] = {tvh[0], tvh[1]}, bh1[2] = {tvh[2], tvh[3]};
                uint32_t bl0[2] = {tvl[0], tvl[1]}, bl1[2] = {tvl[2], tvl[3]};
                mma16816(O[2 * dj],     Ah, bh0);
                mma16816(O[2 * dj + 1], Ah, bh1);
                mma16816(O[2 * dj],     Al, bh0);
                mma16816(O[2 * dj + 1], Al, bh1);
                mma16816(O[2 * dj],     Ah, bl0);
                mma16816(O[2 * dj + 1], Ah, bl1);
            }
        }
    }

    // ---- finalize: l reduce within quad, normalize, write split bf16 ----
    lsum0 += __shfl_xor_sync(0xffffffffu, lsum0, 1);
    lsum0 += __shfl_xor_sync(0xffffffffu, lsum0, 2);
    lsum1 += __shfl_xor_sync(0xffffffffu, lsum1, 1);
    lsum1 += __shfl_xor_sync(0xffffffffu, lsum1, 2);
    float inv0 = 1.0f / lsum0;
    float inv1 = 1.0f / lsum1;

    int r_g = qi * 64 + wq + (lane >> 2);
#pragma unroll
    for (int hh = 0; hh < 2; hh++) {
        float inv = hh ? inv1 : inv0;
        size_t orow = (size_t)(b * TT + r_g + hh * 8) * CC + h * DD + (lane & 3) * 2;
#pragma unroll
        for (int j = 0; j < 8; j++) {
            float v0 = O[j][hh * 2 + 0] * inv;
            float v1 = O[j][hh * 2 + 1] * inv;
            __nv_bfloat16 h0, l0, h1, l1;
            split2(v0, h0, l0);
            split2(v1, h1, l1);
            __nv_bfloat162 hp; hp.x = h0; hp.y = h1;
            __nv_bfloat162 lp; lp.x = l0; lp.y = l1;
            *(__nv_bfloat162*)(outH + orow + j * 8) = hp;
            *(__nv_bfloat162*)(outL + orow + j * 8) = lp;
        }
    }
}

// ---------------------------------------------------------------------------
// Fixup: rows t < first_unpadded[b] softmax uniformly over ALL padded
// columns (incl. future) -> out = mean of V over padded positions.
// ---------------------------------------------------------------------------
__global__ __launch_bounds__(256) void fixup_kernel(
    const __nv_bfloat16* __restrict__ qkvH,
    const __nv_bfloat16* __restrict__ qkvL,
    const int* __restrict__ mask,
    __nv_bfloat16* __restrict__ outH,
    __nv_bfloat16* __restrict__ outL)
{
    int b = blockIdx.x;
    int f = g_fu[b];
    if (f == 0) return;
    int tid = threadIdx.x;
    float sum[4] = {0, 0, 0, 0};
    int cnt = 0;
    for (int s = 0; s < TT; s++) {
        if (mask[b * TT + s]) {
            cnt++;
            size_t base = (size_t)(b * TT + s) * (3 * CC) + 2 * CC + tid * 4;
#pragma unroll
            for (int e = 0; e < 4; e++)
                sum[e] += __bfloat162float(qkvH[base + e]) +
                          __bfloat162float(qkvL[base + e]);
        }
    }
    float invc = 1.0f / (float)cnt;
    __nv_bfloat16 mh[4], ml[4];
#pragma unroll
    for (int e = 0; e < 4; e++) split2(sum[e] * invc, mh[e], ml[e]);
    for (int t = 0; t < f; t++) {
        size_t o = (size_t)(b * TT + t) * CC + tid * 4;
#pragma unroll
        for (int e = 0; e < 4; e++) {
            outH[o + e] = mh[e];
            outL[o + e] = ml[e];
        }
    }
}

// ---------------------------------------------------------------------------
// Launch
// ---------------------------------------------------------------------------
extern "C" void kernel_launch(void* const* d_in, const int* in_sizes, int n_in,
                              void* d_out, int out_size)
{
    const float* x     = (const float*)d_in[0];
    const void*  pmask = d_in[1];
    const float* Wq    = (const float*)d_in[2];
    const float* Wk    = (const float*)d_in[3];
    const float* Wv    = (const float*)d_in[4];
    const float* Wo    = (const float*)d_in[5];
    const float* bo    = (const float*)d_in[6];
    const float* ln1_g = (const float*)d_in[7];
    const float* ln1_b = (const float*)d_in[8];
    const float* ln2_g = (const float*)d_in[9];
    const float* ln2_b = (const float*)d_in[10];
    const float* W1    = (const float*)d_in[11];
    const float* b1    = (const float*)d_in[12];
    const float* W2    = (const float*)d_in[13];
    const float* b2    = (const float*)d_in[14];
    float* out = (float*)d_out;

    void *p_proj, *p_qkvH, *p_qkvL, *p_hH, *p_hL, *p_atH, *p_atL,
         *p_h2H, *p_h2L, *p_f1H, *p_f1L, *p_wqH, *p_wqL, *p_woH, *p_woL,
         *p_w1H, *p_w1L, *p_w2H, *p_w2L, *p_mask;
    cudaGetSymbolAddress(&p_proj, g_proj);
    cudaGetSymbolAddress(&p_qkvH, g_qkvH);
    cudaGetSymbolAddress(&p_qkvL, g_qkvL);
    cudaGetSymbolAddress(&p_hH,   g_hH);
    cudaGetSymbolAddress(&p_hL,   g_hL);
    cudaGetSymbolAddress(&p_atH,  g_atH);
    cudaGetSymbolAddress(&p_atL,  g_atL);
    cudaGetSymbolAddress(&p_h2H,  g_h2H);
    cudaGetSymbolAddress(&p_h2L,  g_h2L);
    cudaGetSymbolAddress(&p_f1H,  g_f1H);
    cudaGetSymbolAddress(&p_f1L,  g_f1L);
    cudaGetSymbolAddress(&p_wqH,  g_wqH);
    cudaGetSymbolAddress(&p_wqL,  g_wqL);
    cudaGetSymbolAddress(&p_woH,  g_woH);
    cudaGetSymbolAddress(&p_woL,  g_woL);
    cudaGetSymbolAddress(&p_w1H,  g_w1H);
    cudaGetSymbolAddress(&p_w1L,  g_w1L);
    cudaGetSymbolAddress(&p_w2H,  g_w2H);
    cudaGetSymbolAddress(&p_w2L,  g_w2L);
    cudaGetSymbolAddress(&p_mask, g_mask);

    cudaFuncSetAttribute(gemm_mma, cudaFuncAttributeMaxDynamicSharedMemorySize, GEMM_SMEM);
    cudaFuncSetAttribute(attn_mma, cudaFuncAttributeMaxDynamicSharedMemorySize, ATT_SMEM);

    // 1. mask + first-unpadded
    mask_expand_kernel<<<1, 256>>>(pmask, (int*)p_mask);
    // 2. weight prep
    pack_qkv_kernel<<<(3 * CC * CC + 255) / 256, 256>>>(
        Wq, Wk, Wv, (__nv_bfloat16*)p_wqH, (__nv_bfloat16*)p_wqL);
    tsplit_kernel<<<dim3(CC / 32, CC / 32), dim3(32, 8)>>>(
        Wo, (__nv_bfloat16*)p_woH, (__nv_bfloat16*)p_woL, CC, CC);
    tsplit_kernel<<<dim3(FF / 32, CC / 32), dim3(32, 8)>>>(
        W1, (__nv_bfloat16*)p_w1H, (__nv_bfloat16*)p_w1L, CC, FF);
    tsplit_kernel<<<dim3(CC / 32, FF / 32), dim3(32, 8)>>>(
        W2, (__nv_bfloat16*)p_w2H, (__nv_bfloat16*)p_w2L, FF, CC);
    // 3. LN1
    ln_split_kernel<<<MR, 256>>>(x, ln1_g, ln1_b,
                                 (__nv_bfloat16*)p_hH, (__nv_bfloat16*)p_hL);
    // 4. QKV gemm -> split bf16 qkv
    gemm_mma<<<dim3(3 * CC / 128, MR / 128), 256, GEMM_SMEM>>>(
        (__nv_bfloat16*)p_hH, (__nv_bfloat16*)p_hL,
        (__nv_bfloat16*)p_wqH, (__nv_bfloat16*)p_wqL, nullptr,
        nullptr, (__nv_bfloat16*)p_qkvH, (__nv_bfloat16*)p_qkvL, 3 * CC, CC, 0);
    // 5. tensor-core flash attention (causal sweep) + degenerate-row fixup
    attn_mma<<<dim3(TT / 64, BB * HH), 128, ATT_SMEM>>>(
        (const __nv_bfloat16*)p_qkvH, (const __nv_bfloat16*)p_qkvL,
        (const int*)p_mask,
        (__nv_bfloat16*)p_atH, (__nv_bfloat16*)p_atL);
    fixup_kernel<<<BB, 256>>>(
        (const __nv_bfloat16*)p_qkvH, (const __nv_bfloat16*)p_qkvL,
        (const int*)p_mask,
        (__nv_bfloat16*)p_atH, (__nv_bfloat16*)p_atL);
    // 6. Wo projection
    gemm_mma<<<dim3(CC / 128, MR / 128), 256, GEMM_SMEM>>>(
        (__nv_bfloat16*)p_atH, (__nv_bfloat16*)p_atL,
        (__nv_bfloat16*)p_woH, (__nv_bfloat16*)p_woL, bo,
        (float*)p_proj, nullptr, nullptr, CC, CC, 0);
    // 7. LN2
    ln_split_kernel<<<MR, 256>>>((const float*)p_proj, ln2_g, ln2_b,
                                 (__nv_bfloat16*)p_h2H, (__nv_bfloat16*)p_h2L);
    // 8. FFN1 + relu
    gemm_mma<<<dim3(FF / 128, MR / 128), 256, GEMM_SMEM>>>(
        (__nv_bfloat16*)p_h2H, (__nv_bfloat16*)p_h2L,
        (__nv_bfloat16*)p_w1H, (__nv_bfloat16*)p_w1L, b1,
        nullptr, (__nv_bfloat16*)p_f1H, (__nv_bfloat16*)p_f1L, FF, CC, 1);
    // 9. FFN2 -> d_out
    gemm_mma<<<dim3(CC / 128, MR / 128), 256, GEMM_SMEM>>>(
        (__nv_bfloat16*)p_f1H, (__nv_bfloat16*)p_f1L,
        (__nv_bfloat16*)p_w2H, (__nv_bfloat16*)p_w2L, b2,
        out, nullptr, nullptr, CC, FF, 0);
}

// round 5
// speedup vs baseline: 2.2610x; 1.0406x over previous
#include <cuda_runtime.h>
#include <cuda_bf16.h>
#include <cstdint>
#include <math.h>

// Problem dims
#define BB 4
#define TT 1024
#define CC 1024
#define HH 16
#define DD 64
#define FF 4096
#define MR 4096   // B*T

// ---------------------------------------------------------------------------
// Scratch (static device globals)
// ---------------------------------------------------------------------------
__device__ __align__(256) float g_proj[MR * CC];
__device__ __align__(256) __nv_bfloat16 g_qkvH[MR * 3 * CC];
__device__ __align__(256) __nv_bfloat16 g_qkvL[MR * 3 * CC];
__device__ __align__(256) __nv_bfloat16 g_hH [MR * CC];
__device__ __align__(256) __nv_bfloat16 g_hL [MR * CC];
__device__ __align__(256) __nv_bfloat16 g_atH[MR * CC];
__device__ __align__(256) __nv_bfloat16 g_atL[MR * CC];
__device__ __align__(256) __nv_bfloat16 g_h2H[MR * CC];
__device__ __align__(256) __nv_bfloat16 g_h2L[MR * CC];
__device__ __align__(256) __nv_bfloat16 g_f1H[MR * FF];
__device__ __align__(256) __nv_bfloat16 g_f1L[MR * FF];
__device__ __align__(256) __nv_bfloat16 g_wqH[3 * CC * CC];
__device__ __align__(256) __nv_bfloat16 g_wqL[3 * CC * CC];
__device__ __align__(256) __nv_bfloat16 g_woH[CC * CC];
__device__ __align__(256) __nv_bfloat16 g_woL[CC * CC];
__device__ __align__(256) __nv_bfloat16 g_w1H[FF * CC];
__device__ __align__(256) __nv_bfloat16 g_w1L[FF * CC];
__device__ __align__(256) __nv_bfloat16 g_w2H[CC * FF];
__device__ __align__(256) __nv_bfloat16 g_w2L[CC * FF];
__device__ int g_mask[MR];
__device__ int g_fu[BB];

// ---------------------------------------------------------------------------
// Helpers
// ---------------------------------------------------------------------------
__device__ __forceinline__ uint32_t smem_u32(const void* p) {
    uint32_t a;
    asm("{ .reg .u64 t; cvta.to.shared.u64 t, %1; cvt.u32.u64 %0, t; }" : "=r"(a) : "l"(p));
    return a;
}
__device__ __forceinline__ void cp16(uint32_t s, const void* g) {
    asm volatile("cp.async.cg.shared.global [%0], [%1], 16;" :: "r"(s), "l"(g));
}
#define CP_COMMIT() asm volatile("cp.async.commit_group;" ::: "memory")
#define CP_WAIT1()  asm volatile("cp.async.wait_group 1;"  ::: "memory")
#define CP_WAIT0()  asm volatile("cp.async.wait_group 0;"  ::: "memory")

#define LDSM4(r, addr) \
    asm volatile("ldmatrix.sync.aligned.m8n8.x4.shared.b16 {%0,%1,%2,%3}, [%4];" \
        : "=r"((r)[0]), "=r"((r)[1]), "=r"((r)[2]), "=r"((r)[3]) : "r"(addr))
#define LDSM4T(r, addr) \
    asm volatile("ldmatrix.sync.aligned.m8n8.x4.trans.shared.b16 {%0,%1,%2,%3}, [%4];" \
        : "=r"((r)[0]), "=r"((r)[1]), "=r"((r)[2]), "=r"((r)[3]) : "r"(addr))

__device__ __forceinline__ void mma16816(float* c, const uint32_t* a, const uint32_t* b) {
    asm volatile("mma.sync.aligned.m16n8k16.row.col.f32.bf16.bf16.f32 "
        "{%0,%1,%2,%3}, {%4,%5,%6,%7}, {%8,%9}, {%0,%1,%2,%3};"
        : "+f"(c[0]), "+f"(c[1]), "+f"(c[2]), "+f"(c[3])
        : "r"(a[0]), "r"(a[1]), "r"(a[2]), "r"(a[3]), "r"(b[0]), "r"(b[1]));
}

__device__ __forceinline__ void split2(float v, __nv_bfloat16& h, __nv_bfloat16& l) {
    h = __float2bfloat16(v);
    l = __float2bfloat16(v - __bfloat162float(h));
}
__device__ __forceinline__ float fex2(float x) {
    float r;
    asm("ex2.approx.ftz.f32 %0, %1;" : "=f"(r) : "f"(x));
    return r;
}

// ---------------------------------------------------------------------------
// Mask classify + expand + first-unpadded per batch
// ---------------------------------------------------------------------------
__global__ void mask_expand_kernel(const void* __restrict__ pm, int* __restrict__ out)
{
    int tid = threadIdx.x;
    if (tid < BB) g_fu[tid] = TT;
    const unsigned* w = (const unsigned*)pm;
    int li = 0, lf = 0;
    for (int i = tid; i < 1024; i += 256) {
        unsigned v = w[i];
        li |= (v > 1u);
        lf |= (v != 0u && v != 0x3F800000u);
    }
    int not_int = __syncthreads_or(li);
    int not_flt = __syncthreads_or(lf);
    int cls = (!not_int) ? 0 : ((!not_flt) ? 1 : 2);
    for (int i = tid; i < MR; i += 256) {
        int m;
        if (cls == 0)      m = (((const int*)pm)[i] != 0);
        else if (cls == 1) m = (((const float*)pm)[i] != 0.0f);
        else               m = (((const unsigned char*)pm)[i] != 0);
        out[i] = m;
        if (!m) atomicMin(&g_fu[i >> 10], i & 1023);
    }
}

// ---------------------------------------------------------------------------
// Pack Wq/Wk/Wv (H,C,D) -> transposed split (3C, C) bf16 hi/lo
// ---------------------------------------------------------------------------
__global__ void pack_qkv_kernel(const float* __restrict__ Wq,
                                const float* __restrict__ Wk,
                                const float* __restrict__ Wv,
                                __nv_bfloat16* __restrict__ oh,
                                __nv_bfloat16* __restrict__ ol)
{
    int idx = blockIdx.x * blockDim.x + threadIdx.x;
    if (idx >= 3 * CC * CC) return;
    int j = idx / CC;
    int c = idx % CC;
    const float* W = (j < CC) ? Wq : (j < 2 * CC) ? Wk : Wv;
    int jj = j & (CC - 1);
    int h = jj >> 6, d = jj & 63;
    float v = W[(h * CC + c) * DD + d];
    __nv_bfloat16 hh, ll; split2(v, hh, ll);
    oh[idx] = hh; ol[idx] = ll;
}

// ---------------------------------------------------------------------------
// Tiled transpose + split
// ---------------------------------------------------------------------------
__global__ void tsplit_kernel(const float* __restrict__ in,
                              __nv_bfloat16* __restrict__ oh,
                              __nv_bfloat16* __restrict__ ol,
                              int R, int Cn)
{
    __shared__ float t[32][33];
    int c0 = blockIdx.x * 32, r0 = blockIdx.y * 32;
    int x = threadIdx.x, y = threadIdx.y;
#pragma unroll
    for (int i = 0; i < 32; i += 8)
        t[y + i][x] = in[(size_t)(r0 + y + i) * Cn + c0 + x];
    __syncthreads();
#pragma unroll
    for (int i = 0; i < 32; i += 8) {
        float v = t[x][y + i];
        __nv_bfloat16 h, l; split2(v, h, l);
        size_t o = (size_t)(c0 + y + i) * R + r0 + x;
        oh[o] = h; ol[o] = l;
    }
}

// ---------------------------------------------------------------------------
// LayerNorm + split
// ---------------------------------------------------------------------------
__global__ __launch_bounds__(256) void ln_split_kernel(const float* __restrict__ x,
                                                       const float* __restrict__ g,
                                                       const float* __restrict__ b,
                                                       __nv_bfloat16* __restrict__ oh,
                                                       __nv_bfloat16* __restrict__ ol)
{
    int row = blockIdx.x, tid = threadIdx.x;
    const float* xr = x + (size_t)row * CC;
    float v[4];
    float s = 0.f, ss = 0.f;
#pragma unroll
    for (int i = 0; i < 4; i++) {
        v[i] = xr[tid + i * 256];
        s += v[i];
        ss += v[i] * v[i];
    }
#pragma unroll
    for (int o = 16; o; o >>= 1) {
        s  += __shfl_xor_sync(0xffffffffu, s,  o);
        ss += __shfl_xor_sync(0xffffffffu, ss, o);
    }
    __shared__ float ws[8], wss[8];
    __shared__ float s_m, s_r;
    int wid = tid >> 5;
    if ((tid & 31) == 0) { ws[wid] = s; wss[wid] = ss; }
    __syncthreads();
    if (tid == 0) {
        float S = 0.f, SS = 0.f;
        for (int i = 0; i < 8; i++) { S += ws[i]; SS += wss[i]; }
        float m = S * (1.0f / CC);
        float var = SS * (1.0f / CC) - m * m;
        s_m = m;
        s_r = rsqrtf(var + 1e-5f);
    }
    __syncthreads();
    float m = s_m, r = s_r;
#pragma unroll
    for (int i = 0; i < 4; i++) {
        int c = tid + i * 256;
        float o = (v[i] - m) * r * g[c] + b[c];
        __nv_bfloat16 hh, ll; split2(o, hh, ll);
        size_t idx = (size_t)row * CC + c;
        oh[idx] = hh; ol[idx] = ll;
    }
}

// ---------------------------------------------------------------------------
// mma.sync bf16 GEMM (as R3/R4)
// ---------------------------------------------------------------------------
#define PITCH 72
#define TILE_B (128 * PITCH * 2)
#define STAGE_B (4 * TILE_B)
#define GEMM_SMEM (2 * STAGE_B)

__global__ __launch_bounds__(256, 1) void gemm_mma(
    const __nv_bfloat16* __restrict__ Ah, const __nv_bfloat16* __restrict__ Al,
    const __nv_bfloat16* __restrict__ Bh, const __nv_bfloat16* __restrict__ Bl,
    const float* __restrict__ bias,
    float* __restrict__ outF,
    __nv_bfloat16* __restrict__ outH, __nv_bfloat16* __restrict__ outL,
    int Ntot, int Ktot, int relu)
{
    extern __shared__ __align__(128) char smem[];
    const uint32_t sb0 = smem_u32(smem);
    int tid = threadIdx.x, lane = tid & 31, w = tid >> 5;
    int bm = blockIdx.y * 128, bn = blockIdx.x * 128;
    int wm = (w & 1) * 64, wn = (w >> 1) * 32;
    int nk = Ktot >> 6;

    int q_r[4], q_c[4];
#pragma unroll
    for (int i = 0; i < 4; i++) {
        int q = tid + i * 256;
        q_r[i] = q >> 3;
        q_c[i] = (q & 7) * 8;
    }

    float acc[4][4][4] = {};

    auto load_stage = [&](int st, int kc) {
        uint32_t sb = sb0 + st * STAGE_B;
#pragma unroll
        for (int i = 0; i < 4; i++) {
            int r = q_r[i], c = q_c[i];
            uint32_t so = (uint32_t)(r * PITCH + c) * 2;
            size_t goA = (size_t)(bm + r) * Ktot + kc + c;
            size_t goB = (size_t)(bn + r) * Ktot + kc + c;
            cp16(sb + so,              Ah + goA);
            cp16(sb + TILE_B + so,     Al + goA);
            cp16(sb + 2 * TILE_B + so, Bh + goB);
            cp16(sb + 3 * TILE_B + so, Bl + goB);
        }
    };

    load_stage(0, 0);
    CP_COMMIT();

    int lrow = lane & 15;
    int lk = (lane >> 4) * 8;

    for (int kc = 0; kc < nk; kc++) {
        if (kc + 1 < nk) {
            load_stage((kc + 1) & 1, (kc + 1) * 64);
            CP_COMMIT();
            CP_WAIT1();
        } else {
            CP_WAIT0();
        }
        __syncthreads();

        uint32_t sb = sb0 + (kc & 1) * STAGE_B;
#pragma unroll
        for (int ks = 0; ks < 4; ks++) {
            int k0 = ks * 16;
            uint32_t ah[4][4], al[4][4], bh[4][2], bl[4][2];
#pragma unroll
            for (int i = 0; i < 4; i++) {
                uint32_t ad = sb + (uint32_t)((wm + i * 16 + lrow) * PITCH + k0 + lk) * 2;
                LDSM4(ah[i], ad);
                LDSM4(al[i], ad + TILE_B);
            }
#pragma unroll
            for (int jj = 0; jj < 2; jj++) {
                uint32_t bd = sb + 2 * TILE_B +
                              (uint32_t)((wn + jj * 16 + lrow) * PITCH + k0 + lk) * 2;
                uint32_t t[4];
                LDSM4(t, bd);
                bh[jj * 2][0] = t[0]; bh[jj * 2][1] = t[2];
                bh[jj * 2 + 1][0] = t[1]; bh[jj * 2 + 1][1] = t[3];
                LDSM4(t, bd + TILE_B);
                bl[jj * 2][0] = t[0]; bl[jj * 2][1] = t[2];
                bl[jj * 2 + 1][0] = t[1]; bl[jj * 2 + 1][1] = t[3];
            }
#pragma unroll
            for (int i = 0; i < 4; i++)
#pragma unroll
                for (int j = 0; j < 4; j++)
                    mma16816(acc[i][j], ah[i], bh[j]);
#pragma unroll
            for (int i = 0; i < 4; i++)
#pragma unroll
                for (int j = 0; j < 4; j++)
                    mma16816(acc[i][j], al[i], bh[j]);
#pragma unroll
            for (int i = 0; i < 4; i++)
#pragma unroll
                for (int j = 0; j < 4; j++)
                    mma16816(acc[i][j], ah[i], bl[j]);
        }
        __syncthreads();
    }

#pragma unroll
    for (int i = 0; i < 4; i++) {
        int r0 = bm + wm + i * 16 + (lane >> 2);
#pragma unroll
        for (int j = 0; j < 4; j++) {
            int c = bn + wn + j * 8 + (lane & 3) * 2;
            float bx0 = bias ? bias[c] : 0.0f;
            float bx1 = bias ? bias[c + 1] : 0.0f;
#pragma unroll
            for (int hh = 0; hh < 2; hh++) {
                int r = r0 + hh * 8;
                float v0 = acc[i][j][hh * 2 + 0] + bx0;
                float v1 = acc[i][j][hh * 2 + 1] + bx1;
                if (relu) { v0 = fmaxf(v0, 0.0f); v1 = fmaxf(v1, 0.0f); }
                size_t o = (size_t)r * Ntot + c;
                if (outF) {
                    outF[o] = v0;
                    outF[o + 1] = v1;
                } else {
                    __nv_bfloat16 h0, l0, h1, l1;
                    split2(v0, h0, l0);
                    split2(v1, h1, l1);
                    __nv_bfloat162 hp; hp.x = h0; hp.y = h1;
                    __nv_bfloat162 lp; lp.x = l0; lp.y = l1;
                    *(__nv_bfloat162*)(outH + o) = hp;
                    *(__nv_bfloat162*)(outL + o) = lp;
                }
            }
        }
    }
}

// ---------------------------------------------------------------------------
// Tensor-core flash attention v2:
//  - CTA = 256 threads (8 warps), q-tile 128 rows, s-tile 64.
//  - double-buffered cp.async pipeline over (Kh, Vh, Vl, mask).
//  - QK^T 2-pass (Qh+Ql vs Kh only); PV 3-pass.
//  - causal-only sweep; degenerate rows fixed up afterwards.
// ---------------------------------------------------------------------------
#define AT_PITCH 72
#define AQ_TILEB (128 * AT_PITCH * 2)     // 18432
#define AKV_TILEB (64 * AT_PITCH * 2)     // 9216
#define SMASK_OFF (2 * AQ_TILEB + 6 * AKV_TILEB)   // 92160
#define ATT_SMEM (SMASK_OFF + 2 * 64 * 4)          // 92672

__global__ __launch_bounds__(256) void attn_mma(
    const __nv_bfloat16* __restrict__ qkvH,
    const __nv_bfloat16* __restrict__ qkvL,
    const int* __restrict__ mask,
    __nv_bfloat16* __restrict__ outH,
    __nv_bfloat16* __restrict__ outL)
{
    extern __shared__ __align__(128) char smem[];
    const uint32_t sb = smem_u32(smem);
    const uint32_t sQh = sb, sQl = sb + AQ_TILEB;

    int qi = blockIdx.x;               // q block of 128 rows (0..7)
    int bh = blockIdx.y;
    int b = bh >> 4, h = bh & 15;
    int tid = threadIdx.x, lane = tid & 31, w = tid >> 5;
    int wq = w * 16;
    int lrow = lane & 15, lkc = (lane >> 4) * 8;

    const size_t rowbase = (size_t)(b * TT) * (3 * CC) + h * DD;
    const int* gmask = mask + b * TT;
    int* smask = (int*)(smem + SMASK_OFF);

    // ---- Q tile (hi+lo), 8 cp16 per thread ----
#pragma unroll
    for (int i = 0; i < 4; i++) {
        int idx = tid + i * 256;
        int r = idx >> 3, ch = (idx & 7) * 8;
        uint32_t so = (uint32_t)(r * AT_PITCH + ch) * 2;
        size_t go = rowbase + (size_t)(qi * 128 + r) * (3 * CC) + ch;
        cp16(sQh + so, qkvH + go);
        cp16(sQl + so, qkvL + go);
    }

    // ---- stage loader: Kh, Vh, Vl, mask for s-tile sj ----
    auto load_stage = [&](int sj) {
        int st = sj & 1;
        uint32_t base = sb + 2 * AQ_TILEB + st * (3 * AKV_TILEB);
#pragma unroll
        for (int i = 0; i < 6; i++) {
            int idx = tid + i * 256;          // 0..1535
            int tile = idx >> 9;              // 0:Kh 1:Vh 2:Vl
            int rem = idx & 511;
            int r = rem >> 3, ch = (rem & 7) * 8;
            uint32_t so = base + tile * AKV_TILEB + (uint32_t)(r * AT_PITCH + ch) * 2;
            size_t gk = rowbase + (size_t)(sj * 64 + r) * (3 * CC) + CC + ch;
            if (tile == 0)      cp16(so, qkvH + gk);
            else if (tile == 1) cp16(so, qkvH + gk + CC);
            else                cp16(so, qkvL + gk + CC);
        }
        if (tid < 16)
            cp16(sb + SMASK_OFF + st * 256 + tid * 16, gmask + sj * 64 + tid * 4);
    };

    int ns = 2 * qi + 2;
    load_stage(0);
    CP_COMMIT();

    float O[8][4];
#pragma unroll
    for (int j = 0; j < 8; j++)
#pragma unroll
        for (int e = 0; e < 4; e++) O[j][e] = 0.0f;
    float lsum0 = 0.0f, lsum1 = 0.0f;

    const float csc = 0.0450842200f;   // log2(e) / 32
    const int t_base = qi * 128 + wq + (lane >> 2);

    for (int sj = 0; sj < ns; sj++) {
        int cur = sj & 1;
        if (sj + 1 < ns) {
            load_stage(sj + 1);
            CP_COMMIT();
            CP_WAIT1();
        } else {
            CP_WAIT0();
        }
        __syncthreads();

        uint32_t kvb = sb + 2 * AQ_TILEB + cur * (3 * AKV_TILEB);
        uint32_t sKh = kvb, sVh = kvb + AKV_TILEB, sVl = kvb + 2 * AKV_TILEB;
        const int* mrow = smask + cur * 64;

        // ---- S = Q K^T (2-pass: Qh·Kh + Ql·Kh) ----
        float S[8][4];
#pragma unroll
        for (int j = 0; j < 8; j++)
#pragma unroll
            for (int e = 0; e < 4; e++) S[j][e] = 0.0f;

#pragma unroll
        for (int ks = 0; ks < 4; ks++) {
            uint32_t qa[4], ql[4];
            uint32_t ad = sQh + (uint32_t)((wq + lrow) * AT_PITCH + ks * 16 + lkc) * 2;
            LDSM4(qa, ad);
            LDSM4(ql, ad + AQ_TILEB);
#pragma unroll
            for (int nj = 0; nj < 4; nj++) {
                uint32_t bd = sKh + (uint32_t)((nj * 16 + lrow) * AT_PITCH + ks * 16 + lkc) * 2;
                uint32_t th[4];
                LDSM4(th, bd);
                uint32_t bh0[2] = {th[0], th[2]}, bh1[2] = {th[1], th[3]};
                mma16816(S[2 * nj],     qa, bh0);
                mma16816(S[2 * nj + 1], qa, bh1);
                mma16816(S[2 * nj],     ql, bh0);
                mma16816(S[2 * nj + 1], ql, bh1);
            }
        }

        // ---- mask + exp2 ----
#pragma unroll
        for (int j = 0; j < 8; j++) {
            int s0 = sj * 64 + j * 8 + (lane & 3) * 2;
#pragma unroll
            for (int e = 0; e < 4; e++) {
                int s_g = s0 + (e & 1);
                int t_g = t_base + (e >> 1) * 8;
                float v = S[j][e] * csc;
                if (mrow[s_g - sj * 64] || (s_g > t_g)) v = -1e9f;
                S[j][e] = fex2(v);
            }
            lsum0 += S[j][0] + S[j][1];
            lsum1 += S[j][2] + S[j][3];
        }

        // ---- pack P (hi/lo) ----
        uint32_t aPh[8][2], aPl[8][2];
#pragma unroll
        for (int j = 0; j < 8; j++) {
            __nv_bfloat162 h0 = __floats2bfloat162_rn(S[j][0], S[j][1]);
            __nv_bfloat162 h1 = __floats2bfloat162_rn(S[j][2], S[j][3]);
            float r00 = S[j][0] - __bfloat162float(h0.x);
            float r01 = S[j][1] - __bfloat162float(h0.y);
            float r10 = S[j][2] - __bfloat162float(h1.x);
            float r11 = S[j][3] - __bfloat162float(h1.y);
            __nv_bfloat162 l0 = __floats2bfloat162_rn(r00, r01);
            __nv_bfloat162 l1 = __floats2bfloat162_rn(r10, r11);
            aPh[j][0] = *(uint32_t*)&h0; aPh[j][1] = *(uint32_t*)&h1;
            aPl[j][0] = *(uint32_t*)&l0; aPl[j][1] = *(uint32_t*)&l1;
        }

        // ---- O += P V (3-pass) ----
#pragma unroll
        for (int kc = 0; kc < 4; kc++) {
            uint32_t Ahf[4] = {aPh[2 * kc][0], aPh[2 * kc][1],
                               aPh[2 * kc + 1][0], aPh[2 * kc + 1][1]};
            uint32_t Alf[4] = {aPl[2 * kc][0], aPl[2 * kc][1],
                               aPl[2 * kc + 1][0], aPl[2 * kc + 1][1]};
#pragma unroll
            for (int dj = 0; dj < 4; dj++) {
                uint32_t vd = sVh + (uint32_t)((kc * 16 + lrow) * AT_PITCH + dj * 16 + lkc) * 2;
                uint32_t tvh[4], tvl[4];
                LDSM4T(tvh, vd);
                LDSM4T(tvl, vd + AKV_TILEB);
                uint32_t bh0[2] = {tvh[0], tvh[1]}, bh1[2] = {tvh[2], tvh[3]};
                uint32_t bl0[2] = {tvl[0], tvl[1]}, bl1[2] = {tvl[2], tvl[3]};
                mma16816(O[2 * dj],     Ahf, bh0);
                mma16816(O[2 * dj + 1], Ahf, bh1);
                mma16816(O[2 * dj],     Alf, bh0);
                mma16816(O[2 * dj + 1], Alf, bh1);
                mma16816(O[2 * dj],     Ahf, bl0);
                mma16816(O[2 * dj + 1], Ahf, bl1);
            }
        }
        __syncthreads();
    }

    // ---- finalize ----
    lsum0 += __shfl_xor_sync(0xffffffffu, lsum0, 1);
    lsum0 += __shfl_xor_sync(0xffffffffu, lsum0, 2);
    lsum1 += __shfl_xor_sync(0xffffffffu, lsum1, 1);
    lsum1 += __shfl_xor_sync(0xffffffffu, lsum1, 2);
    float inv0 = 1.0f / lsum0;
    float inv1 = 1.0f / lsum1;

#pragma unroll
    for (int hh = 0; hh < 2; hh++) {
        float inv = hh ? inv1 : inv0;
        size_t orow = (size_t)(b * TT + t_base + hh * 8) * CC + h * DD + (lane & 3) * 2;
#pragma unroll
        for (int j = 0; j < 8; j++) {
            float v0 = O[j][hh * 2 + 0] * inv;
            float v1 = O[j][hh * 2 + 1] * inv;
            __nv_bfloat16 h0, l0, h1, l1;
            split2(v0, h0, l0);
            split2(v1, h1, l1);
            __nv_bfloat162 hp; hp.x = h0; hp.y = h1;
            __nv_bfloat162 lp; lp.x = l0; lp.y = l1;
            *(__nv_bfloat162*)(outH + orow + j * 8) = hp;
            *(__nv_bfloat162*)(outL + orow + j * 8) = lp;
        }
    }
}

// ---------------------------------------------------------------------------
// Fixup: rows t < first_unpadded[b] -> out = mean of V over padded positions.
// ---------------------------------------------------------------------------
__global__ __launch_bounds__(256) void fixup_kernel(
    const __nv_bfloat16* __restrict__ qkvH,
    const __nv_bfloat16* __restrict__ qkvL,
    const int* __restrict__ mask,
    __nv_bfloat16* __restrict__ outH,
    __nv_bfloat16* __restrict__ outL)
{
    int b = blockIdx.x;
    int f = g_fu[b];
    if (f == 0) return;
    int tid = threadIdx.x;
    float sum[4] = {0, 0, 0, 0};
    int cnt = 0;
    for (int s = 0; s < TT; s++) {
        if (mask[b * TT + s]) {
            cnt++;
            size_t base = (size_t)(b * TT + s) * (3 * CC) + 2 * CC + tid * 4;
#pragma unroll
            for (int e = 0; e < 4; e++)
                sum[e] += __bfloat162float(qkvH[base + e]) +
                          __bfloat162float(qkvL[base + e]);
        }
    }
    float invc = 1.0f / (float)cnt;
    __nv_bfloat16 mh[4], ml[4];
#pragma unroll
    for (int e = 0; e < 4; e++) split2(sum[e] * invc, mh[e], ml[e]);
    for (int t = 0; t < f; t++) {
        size_t o = (size_t)(b * TT + t) * CC + tid * 4;
#pragma unroll
        for (int e = 0; e < 4; e++) {
            outH[o + e] = mh[e];
            outL[o + e] = ml[e];
        }
    }
}

// ---------------------------------------------------------------------------
// Launch
// ---------------------------------------------------------------------------
extern "C" void kernel_launch(void* const* d_in, const int* in_sizes, int n_in,
                              void* d_out, int out_size)
{
    const float* x     = (const float*)d_in[0];
    const void*  pmask = d_in[1];
    const float* Wq    = (const float*)d_in[2];
    const float* Wk    = (const float*)d_in[3];
    const float* Wv    = (const float*)d_in[4];
    const float* Wo    = (const float*)d_in[5];
    const float* bo    = (const float*)d_in[6];
    const float* ln1_g = (const float*)d_in[7];
    const float* ln1_b = (const float*)d_in[8];
    const float* ln2_g = (const float*)d_in[9];
    const float* ln2_b = (const float*)d_in[10];
    const float* W1    = (const float*)d_in[11];
    const float* b1    = (const float*)d_in[12];
    const float* W2    = (const float*)d_in[13];
    const float* b2    = (const float*)d_in[14];
    float* out = (float*)d_out;

    void *p_proj, *p_qkvH, *p_qkvL, *p_hH, *p_hL, *p_atH, *p_atL,
         *p_h2H, *p_h2L, *p_f1H, *p_f1L, *p_wqH, *p_wqL, *p_woH, *p_woL,
         *p_w1H, *p_w1L, *p_w2H, *p_w2L, *p_mask;
    cudaGetSymbolAddress(&p_proj, g_proj);
    cudaGetSymbolAddress(&p_qkvH, g_qkvH);
    cudaGetSymbolAddress(&p_qkvL, g_qkvL);
    cudaGetSymbolAddress(&p_hH,   g_hH);
    cudaGetSymbolAddress(&p_hL,   g_hL);
    cudaGetSymbolAddress(&p_atH,  g_atH);
    cudaGetSymbolAddress(&p_atL,  g_atL);
    cudaGetSymbolAddress(&p_h2H,  g_h2H);
    cudaGetSymbolAddress(&p_h2L,  g_h2L);
    cudaGetSymbolAddress(&p_f1H,  g_f1H);
    cudaGetSymbolAddress(&p_f1L,  g_f1L);
    cudaGetSymbolAddress(&p_wqH,  g_wqH);
    cudaGetSymbolAddress(&p_wqL,  g_wqL);
    cudaGetSymbolAddress(&p_woH,  g_woH);
    cudaGetSymbolAddress(&p_woL,  g_woL);
    cudaGetSymbolAddress(&p_w1H,  g_w1H);
    cudaGetSymbolAddress(&p_w1L,  g_w1L);
    cudaGetSymbolAddress(&p_w2H,  g_w2H);
    cudaGetSymbolAddress(&p_w2L,  g_w2L);
    cudaGetSymbolAddress(&p_mask, g_mask);

    cudaFuncSetAttribute(gemm_mma, cudaFuncAttributeMaxDynamicSharedMemorySize, GEMM_SMEM);
    cudaFuncSetAttribute(attn_mma, cudaFuncAttributeMaxDynamicSharedMemorySize, ATT_SMEM);

    // 1. mask + first-unpadded
    mask_expand_kernel<<<1, 256>>>(pmask, (int*)p_mask);
    // 2. weight prep
    pack_qkv_kernel<<<(3 * CC * CC + 255) / 256, 256>>>(
        Wq, Wk, Wv, (__nv_bfloat16*)p_wqH, (__nv_bfloat16*)p_wqL);
    tsplit_kernel<<<dim3(CC / 32, CC / 32), dim3(32, 8)>>>(
        Wo, (__nv_bfloat16*)p_woH, (__nv_bfloat16*)p_woL, CC, CC);
    tsplit_kernel<<<dim3(FF / 32, CC / 32), dim3(32, 8)>>>(
        W1, (__nv_bfloat16*)p_w1H, (__nv_bfloat16*)p_w1L, CC, FF);
    tsplit_kernel<<<dim3(CC / 32, FF / 32), dim3(32, 8)>>>(
        W2, (__nv_bfloat16*)p_w2H, (__nv_bfloat16*)p_w2L, FF, CC);
    // 3. LN1
    ln_split_kernel<<<MR, 256>>>(x, ln1_g, ln1_b,
                                 (__nv_bfloat16*)p_hH, (__nv_bfloat16*)p_hL);
    // 4. QKV gemm -> split bf16 qkv
    gemm_mma<<<dim3(3 * CC / 128, MR / 128), 256, GEMM_SMEM>>>(
        (__nv_bfloat16*)p_hH, (__nv_bfloat16*)p_hL,
        (__nv_bfloat16*)p_wqH, (__nv_bfloat16*)p_wqL, nullptr,
        nullptr, (__nv_bfloat16*)p_qkvH, (__nv_bfloat16*)p_qkvL, 3 * CC, CC, 0);
    // 5. flash attention (pipelined) + fixup
    attn_mma<<<dim3(TT / 128, BB * HH), 256, ATT_SMEM>>>(
        (const __nv_bfloat16*)p_qkvH, (const __nv_bfloat16*)p_qkvL,
        (const int*)p_mask,
        (__nv_bfloat16*)p_atH, (__nv_bfloat16*)p_atL);
    fixup_kernel<<<BB, 256>>>(
        (const __nv_bfloat16*)p_qkvH, (const __nv_bfloat16*)p_qkvL,
        (const int*)p_mask,
        (__nv_bfloat16*)p_atH, (__nv_bfloat16*)p_atL);
    // 6. Wo projection
    gemm_mma<<<dim3(CC / 128, MR / 128), 256, GEMM_SMEM>>>(
        (__nv_bfloat16*)p_atH, (__nv_bfloat16*)p_atL,
        (__nv_bfloat16*)p_woH, (__nv_bfloat16*)p_woL, bo,
        (float*)p_proj, nullptr, nullptr, CC, CC, 0);
    // 7. LN2
    ln_split_kernel<<<MR, 256>>>((const float*)p_proj, ln2_g, ln2_b,
                                 (__nv_bfloat16*)p_h2H, (__nv_bfloat16*)p_h2L);
    // 8. FFN1 + relu
    gemm_mma<<<dim3(FF / 128, MR / 128), 256, GEMM_SMEM>>>(
        (__nv_bfloat16*)p_h2H, (__nv_bfloat16*)p_h2L,
        (__nv_bfloat16*)p_w1H, (__nv_bfloat16*)p_w1L, b1,
        nullptr, (__nv_bfloat16*)p_f1H, (__nv_bfloat16*)p_f1L, FF, CC, 1);
    // 9. FFN2 -> d_out
    gemm_mma<<<dim3(CC / 128, MR / 128), 256, GEMM_SMEM>>>(
        (__nv_bfloat16*)p_f1H, (__nv_bfloat16*)p_f1L,
        (__nv_bfloat16*)p_w2H, (__nv_bfloat16*)p_w2L, b2,
        out, nullptr, nullptr, CC, FF, 0);
}

// round 6
// speedup vs baseline: 2.8622x; 1.2659x over previous
#include <cuda_runtime.h>
#include <cuda_fp16.h>
#include <cstdint>
#include <math.h>

// Problem dims
#define BB 4
#define TT 1024
#define CC 1024
#define HH 16
#define DD 64
#define FF 4096
#define MR 4096   // B*T

// ---------------------------------------------------------------------------
// Scratch (static device globals)
// ---------------------------------------------------------------------------
__device__ __align__(256) float g_proj[MR * CC];
__device__ __align__(256) __half g_qkvH[MR * 3 * CC];
__device__ __align__(256) __half g_qkvL[MR * 3 * CC];
__device__ __align__(256) __half g_hH [MR * CC];
__device__ __align__(256) __half g_hL [MR * CC];
__device__ __align__(256) __half g_atH[MR * CC];
__device__ __align__(256) __half g_atL[MR * CC];
__device__ __align__(256) __half g_h2H[MR * CC];
__device__ __align__(256) __half g_h2L[MR * CC];
__device__ __align__(256) __half g_f1H[MR * FF];
__device__ __align__(256) __half g_f1L[MR * FF];
__device__ __align__(256) __half g_wqH[3 * CC * CC];   // Wqkv^T fp16 (3072,1024)
__device__ __align__(256) __half g_woH[CC * CC];       // Wo^T
__device__ __align__(256) __half g_w1H[FF * CC];       // W1^T
__device__ __align__(256) __half g_w2H[CC * FF];       // W2^T
__device__ int g_mask[MR];
__device__ int g_fu[BB];

// ---------------------------------------------------------------------------
// Helpers
// ---------------------------------------------------------------------------
__device__ __forceinline__ uint32_t smem_u32(const void* p) {
    uint32_t a;
    asm("{ .reg .u64 t; cvta.to.shared.u64 t, %1; cvt.u32.u64 %0, t; }" : "=r"(a) : "l"(p));
    return a;
}
__device__ __forceinline__ void cp16(uint32_t s, const void* g) {
    asm volatile("cp.async.cg.shared.global [%0], [%1], 16;" :: "r"(s), "l"(g));
}
#define CP_COMMIT() asm volatile("cp.async.commit_group;" ::: "memory")
#define CP_WAIT1()  asm volatile("cp.async.wait_group 1;"  ::: "memory")
#define CP_WAIT0()  asm volatile("cp.async.wait_group 0;"  ::: "memory")

#define LDSM4(r, addr) \
    asm volatile("ldmatrix.sync.aligned.m8n8.x4.shared.b16 {%0,%1,%2,%3}, [%4];" \
        : "=r"((r)[0]), "=r"((r)[1]), "=r"((r)[2]), "=r"((r)[3]) : "r"(addr))
#define LDSM4T(r, addr) \
    asm volatile("ldmatrix.sync.aligned.m8n8.x4.trans.shared.b16 {%0,%1,%2,%3}, [%4];" \
        : "=r"((r)[0]), "=r"((r)[1]), "=r"((r)[2]), "=r"((r)[3]) : "r"(addr))

__device__ __forceinline__ void mma16816(float* c, const uint32_t* a, const uint32_t* b) {
    asm volatile("mma.sync.aligned.m16n8k16.row.col.f32.f16.f16.f32 "
        "{%0,%1,%2,%3}, {%4,%5,%6,%7}, {%8,%9}, {%0,%1,%2,%3};"
        : "+f"(c[0]), "+f"(c[1]), "+f"(c[2]), "+f"(c[3])
        : "r"(a[0]), "r"(a[1]), "r"(a[2]), "r"(a[3]), "r"(b[0]), "r"(b[1]));
}

__device__ __forceinline__ void split2(float v, __half& h, __half& l) {
    h = __float2half_rn(v);
    l = __float2half_rn(v - __half2float(h));
}
__device__ __forceinline__ float fex2(float x) {
    float r;
    asm("ex2.approx.ftz.f32 %0, %1;" : "=f"(r) : "f"(x));
    return r;
}

// ---------------------------------------------------------------------------
// Mask classify + expand + first-unpadded per batch
// ---------------------------------------------------------------------------
__global__ void mask_expand_kernel(const void* __restrict__ pm, int* __restrict__ out)
{
    int tid = threadIdx.x;
    if (tid < BB) g_fu[tid] = TT;
    const unsigned* w = (const unsigned*)pm;
    int li = 0, lf = 0;
    for (int i = tid; i < 1024; i += 256) {
        unsigned v = w[i];
        li |= (v > 1u);
        lf |= (v != 0u && v != 0x3F800000u);
    }
    int not_int = __syncthreads_or(li);
    int not_flt = __syncthreads_or(lf);
    int cls = (!not_int) ? 0 : ((!not_flt) ? 1 : 2);
    for (int i = tid; i < MR; i += 256) {
        int m;
        if (cls == 0)      m = (((const int*)pm)[i] != 0);
        else if (cls == 1) m = (((const float*)pm)[i] != 0.0f);
        else               m = (((const unsigned char*)pm)[i] != 0);
        out[i] = m;
        if (!m) atomicMin(&g_fu[i >> 10], i & 1023);
    }
}

// ---------------------------------------------------------------------------
// Pack Wq/Wk/Wv (H,C,D) -> transposed (3C, C) fp16
// ---------------------------------------------------------------------------
__global__ void pack_qkv_kernel(const float* __restrict__ Wq,
                                const float* __restrict__ Wk,
                                const float* __restrict__ Wv,
                                __half* __restrict__ oh)
{
    int idx = blockIdx.x * blockDim.x + threadIdx.x;
    if (idx >= 3 * CC * CC) return;
    int j = idx / CC;
    int c = idx % CC;
    const float* W = (j < CC) ? Wq : (j < 2 * CC) ? Wk : Wv;
    int jj = j & (CC - 1);
    int h = jj >> 6, d = jj & 63;
    oh[idx] = __float2half_rn(W[(h * CC + c) * DD + d]);
}

// ---------------------------------------------------------------------------
// Tiled transpose: in (R, Cn) fp32 -> out (Cn, R) fp16
// ---------------------------------------------------------------------------
__global__ void tsplit_kernel(const float* __restrict__ in,
                              __half* __restrict__ oh,
                              int R, int Cn)
{
    __shared__ float t[32][33];
    int c0 = blockIdx.x * 32, r0 = blockIdx.y * 32;
    int x = threadIdx.x, y = threadIdx.y;
#pragma unroll
    for (int i = 0; i < 32; i += 8)
        t[y + i][x] = in[(size_t)(r0 + y + i) * Cn + c0 + x];
    __syncthreads();
#pragma unroll
    for (int i = 0; i < 32; i += 8)
        oh[(size_t)(c0 + y + i) * R + r0 + x] = __float2half_rn(t[x][y + i]);
}

// ---------------------------------------------------------------------------
// LayerNorm + split (fp16 hi/lo)
// ---------------------------------------------------------------------------
__global__ __launch_bounds__(256) void ln_split_kernel(const float* __restrict__ x,
                                                       const float* __restrict__ g,
                                                       const float* __restrict__ b,
                                                       __half* __restrict__ oh,
                                                       __half* __restrict__ ol)
{
    int row = blockIdx.x, tid = threadIdx.x;
    const float* xr = x + (size_t)row * CC;
    float v[4];
    float s = 0.f, ss = 0.f;
#pragma unroll
    for (int i = 0; i < 4; i++) {
        v[i] = xr[tid + i * 256];
        s += v[i];
        ss += v[i] * v[i];
    }
#pragma unroll
    for (int o = 16; o; o >>= 1) {
        s  += __shfl_xor_sync(0xffffffffu, s,  o);
        ss += __shfl_xor_sync(0xffffffffu, ss, o);
    }
    __shared__ float ws[8], wss[8];
    __shared__ float s_m, s_r;
    int wid = tid >> 5;
    if ((tid & 31) == 0) { ws[wid] = s; wss[wid] = ss; }
    __syncthreads();
    if (tid == 0) {
        float S = 0.f, SS = 0.f;
        for (int i = 0; i < 8; i++) { S += ws[i]; SS += wss[i]; }
        float m = S * (1.0f / CC);
        float var = SS * (1.0f / CC) - m * m;
        s_m = m;
        s_r = rsqrtf(var + 1e-5f);
    }
    __syncthreads();
    float m = s_m, r = s_r;
#pragma unroll
    for (int i = 0; i < 4; i++) {
        int c = tid + i * 256;
        float o = (v[i] - m) * r * g[c] + b[c];
        __half hh, ll; split2(o, hh, ll);
        size_t idx = (size_t)row * CC + c;
        oh[idx] = hh; ol[idx] = ll;
    }
}

// ---------------------------------------------------------------------------
// fp16 2-pass GEMM: D = (Ah+Al)(M,K) @ Bh^T, B stored (N,K) fp16.
// CTA 128x128, K-chunk 64, 8 warps, cp.async double buffer (3 tiles/stage).
// ---------------------------------------------------------------------------
#define PITCH 72
#define TILE_B (128 * PITCH * 2)
#define STAGE_B (3 * TILE_B)              // Ah | Al | Bh  (55296)
#define GEMM_SMEM (2 * STAGE_B)           // 110592

__global__ __launch_bounds__(256, 1) void gemm_mma(
    const __half* __restrict__ Ah, const __half* __restrict__ Al,
    const __half* __restrict__ Bh,
    const float* __restrict__ bias,
    float* __restrict__ outF,
    __half* __restrict__ outH, __half* __restrict__ outL,
    int Ntot, int Ktot, int relu)
{
    extern __shared__ __align__(128) char smem[];
    const uint32_t sb0 = smem_u32(smem);
    int tid = threadIdx.x, lane = tid & 31, w = tid >> 5;
    int bm = blockIdx.y * 128, bn = blockIdx.x * 128;
    int wm = (w & 1) * 64, wn = (w >> 1) * 32;
    int nk = Ktot >> 6;

    int q_r[4], q_c[4];
#pragma unroll
    for (int i = 0; i < 4; i++) {
        int q = tid + i * 256;
        q_r[i] = q >> 3;
        q_c[i] = (q & 7) * 8;
    }

    float acc[4][4][4] = {};

    auto load_stage = [&](int st, int kc) {
        uint32_t sb = sb0 + st * STAGE_B;
#pragma unroll
        for (int i = 0; i < 4; i++) {
            int r = q_r[i], c = q_c[i];
            uint32_t so = (uint32_t)(r * PITCH + c) * 2;
            size_t goA = (size_t)(bm + r) * Ktot + kc + c;
            size_t goB = (size_t)(bn + r) * Ktot + kc + c;
            cp16(sb + so,              Ah + goA);
            cp16(sb + TILE_B + so,     Al + goA);
            cp16(sb + 2 * TILE_B + so, Bh + goB);
        }
    };

    load_stage(0, 0);
    CP_COMMIT();

    int lrow = lane & 15;
    int lk = (lane >> 4) * 8;

    for (int kc = 0; kc < nk; kc++) {
        if (kc + 1 < nk) {
            load_stage((kc + 1) & 1, (kc + 1) * 64);
            CP_COMMIT();
            CP_WAIT1();
        } else {
            CP_WAIT0();
        }
        __syncthreads();

        uint32_t sb = sb0 + (kc & 1) * STAGE_B;
#pragma unroll
        for (int ks = 0; ks < 4; ks++) {
            int k0 = ks * 16;
            uint32_t ah[4][4], al[4][4], bh[4][2];
#pragma unroll
            for (int i = 0; i < 4; i++) {
                uint32_t ad = sb + (uint32_t)((wm + i * 16 + lrow) * PITCH + k0 + lk) * 2;
                LDSM4(ah[i], ad);
                LDSM4(al[i], ad + TILE_B);
            }
#pragma unroll
            for (int jj = 0; jj < 2; jj++) {
                uint32_t bd = sb + 2 * TILE_B +
                              (uint32_t)((wn + jj * 16 + lrow) * PITCH + k0 + lk) * 2;
                uint32_t t[4];
                LDSM4(t, bd);
                bh[jj * 2][0] = t[0]; bh[jj * 2][1] = t[2];
                bh[jj * 2 + 1][0] = t[1]; bh[jj * 2 + 1][1] = t[3];
            }
#pragma unroll
            for (int i = 0; i < 4; i++)
#pragma unroll
                for (int j = 0; j < 4; j++)
                    mma16816(acc[i][j], ah[i], bh[j]);
#pragma unroll
            for (int i = 0; i < 4; i++)
#pragma unroll
                for (int j = 0; j < 4; j++)
                    mma16816(acc[i][j], al[i], bh[j]);
        }
        __syncthreads();
    }

#pragma unroll
    for (int i = 0; i < 4; i++) {
        int r0 = bm + wm + i * 16 + (lane >> 2);
#pragma unroll
        for (int j = 0; j < 4; j++) {
            int c = bn + wn + j * 8 + (lane & 3) * 2;
            float bx0 = bias ? bias[c] : 0.0f;
            float bx1 = bias ? bias[c + 1] : 0.0f;
#pragma unroll
            for (int hh = 0; hh < 2; hh++) {
                int r = r0 + hh * 8;
                float v0 = acc[i][j][hh * 2 + 0] + bx0;
                float v1 = acc[i][j][hh * 2 + 1] + bx1;
                if (relu) { v0 = fmaxf(v0, 0.0f); v1 = fmaxf(v1, 0.0f); }
                size_t o = (size_t)r * Ntot + c;
                if (outF) {
                    outF[o] = v0;
                    outF[o + 1] = v1;
                } else {
                    __half h0, l0, h1, l1;
                    split2(v0, h0, l0);
                    split2(v1, h1, l1);
                    __half2 hp; hp.x = h0; hp.y = h1;
                    __half2 lp; lp.x = l0; lp.y = l1;
                    *(__half2*)(outH + o) = hp;
                    *(__half2*)(outL + o) = lp;
                }
            }
        }
    }
}

// ---------------------------------------------------------------------------
// fp16 flash attention:
//  - CTA 256 thr (8 warps), q-tile 128, s-tile 64, causal-only sweep.
//  - stage = {Kh, Vh} + mask, double-buffered cp.async.
//  - QK 2-pass (Qh,Ql vs Kh); PV 2-pass (Ph,Pl vs Vh).
// ---------------------------------------------------------------------------
#define AT_PITCH 72
#define AQ_TILEB (128 * AT_PITCH * 2)     // 18432
#define AKV_TILEB (64 * AT_PITCH * 2)     // 9216
#define SMASK_OFF (2 * AQ_TILEB + 4 * AKV_TILEB)   // 73728
#define ATT_SMEM (SMASK_OFF + 2 * 64 * 4)          // 74240

__global__ __launch_bounds__(256) void attn_mma(
    const __half* __restrict__ qkvH,
    const __half* __restrict__ qkvL,
    const int* __restrict__ mask,
    __half* __restrict__ outH,
    __half* __restrict__ outL)
{
    extern __shared__ __align__(128) char smem[];
    const uint32_t sb = smem_u32(smem);
    const uint32_t sQh = sb, sQl = sb + AQ_TILEB;

    int qi = blockIdx.x;
    int bh = blockIdx.y;
    int b = bh >> 4, h = bh & 15;
    int tid = threadIdx.x, lane = tid & 31, w = tid >> 5;
    int wq = w * 16;
    int lrow = lane & 15, lkc = (lane >> 4) * 8;

    const size_t rowbase = (size_t)(b * TT) * (3 * CC) + h * DD;
    const int* gmask = mask + b * TT;
    int* smask = (int*)(smem + SMASK_OFF);

    // Q tile (hi+lo)
#pragma unroll
    for (int i = 0; i < 4; i++) {
        int idx = tid + i * 256;
        int r = idx >> 3, ch = (idx & 7) * 8;
        uint32_t so = (uint32_t)(r * AT_PITCH + ch) * 2;
        size_t go = rowbase + (size_t)(qi * 128 + r) * (3 * CC) + ch;
        cp16(sQh + so, qkvH + go);
        cp16(sQl + so, qkvL + go);
    }

    // stage loader: Kh, Vh, mask
    auto load_stage = [&](int sj) {
        int st = sj & 1;
        uint32_t base = sb + 2 * AQ_TILEB + st * (2 * AKV_TILEB);
#pragma unroll
        for (int i = 0; i < 4; i++) {
            int idx = tid + i * 256;          // 0..1023
            int tile = idx >> 9;              // 0:Kh 1:Vh
            int rem = idx & 511;
            int r = rem >> 3, ch = (rem & 7) * 8;
            uint32_t so = base + tile * AKV_TILEB + (uint32_t)(r * AT_PITCH + ch) * 2;
            size_t gk = rowbase + (size_t)(sj * 64 + r) * (3 * CC) + CC + ch;
            if (tile == 0) cp16(so, qkvH + gk);
            else           cp16(so, qkvH + gk + CC);
        }
        if (tid < 16)
            cp16(sb + SMASK_OFF + st * 256 + tid * 16, gmask + sj * 64 + tid * 4);
    };

    int ns = 2 * qi + 2;
    load_stage(0);
    CP_COMMIT();

    float O[8][4];
#pragma unroll
    for (int j = 0; j < 8; j++)
#pragma unroll
        for (int e = 0; e < 4; e++) O[j][e] = 0.0f;
    float lsum0 = 0.0f, lsum1 = 0.0f;

    const float csc = 0.0450842200f;   // log2(e) / 32
    const int t_base = qi * 128 + wq + (lane >> 2);

    for (int sj = 0; sj < ns; sj++) {
        int cur = sj & 1;
        if (sj + 1 < ns) {
            load_stage(sj + 1);
            CP_COMMIT();
            CP_WAIT1();
        } else {
            CP_WAIT0();
        }
        __syncthreads();

        uint32_t kvb = sb + 2 * AQ_TILEB + cur * (2 * AKV_TILEB);
        uint32_t sKh = kvb, sVh = kvb + AKV_TILEB;
        const int* mrow = smask + cur * 64;

        // S = Q K^T (2-pass)
        float S[8][4];
#pragma unroll
        for (int j = 0; j < 8; j++)
#pragma unroll
            for (int e = 0; e < 4; e++) S[j][e] = 0.0f;

#pragma unroll
        for (int ks = 0; ks < 4; ks++) {
            uint32_t qa[4], ql[4];
            uint32_t ad = sQh + (uint32_t)((wq + lrow) * AT_PITCH + ks * 16 + lkc) * 2;
            LDSM4(qa, ad);
            LDSM4(ql, ad + AQ_TILEB);
#pragma unroll
            for (int nj = 0; nj < 4; nj++) {
                uint32_t bd = sKh + (uint32_t)((nj * 16 + lrow) * AT_PITCH + ks * 16 + lkc) * 2;
                uint32_t th[4];
                LDSM4(th, bd);
                uint32_t bh0[2] = {th[0], th[2]}, bh1[2] = {th[1], th[3]};
                mma16816(S[2 * nj],     qa, bh0);
                mma16816(S[2 * nj + 1], qa, bh1);
                mma16816(S[2 * nj],     ql, bh0);
                mma16816(S[2 * nj + 1], ql, bh1);
            }
        }

        // mask + exp2
#pragma unroll
        for (int j = 0; j < 8; j++) {
            int s0 = sj * 64 + j * 8 + (lane & 3) * 2;
#pragma unroll
            for (int e = 0; e < 4; e++) {
                int s_g = s0 + (e & 1);
                int t_g = t_base + (e >> 1) * 8;
                float v = S[j][e] * csc;
                if (mrow[s_g - sj * 64] || (s_g > t_g)) v = -1e9f;
                S[j][e] = fex2(v);
            }
            lsum0 += S[j][0] + S[j][1];
            lsum1 += S[j][2] + S[j][3];
        }

        // pack P (hi/lo fp16)
        uint32_t aPh[8][2], aPl[8][2];
#pragma unroll
        for (int j = 0; j < 8; j++) {
            __half2 h0 = __floats2half2_rn(S[j][0], S[j][1]);
            __half2 h1 = __floats2half2_rn(S[j][2], S[j][3]);
            float r00 = S[j][0] - __half2float(h0.x);
            float r01 = S[j][1] - __half2float(h0.y);
            float r10 = S[j][2] - __half2float(h1.x);
            float r11 = S[j][3] - __half2float(h1.y);
            __half2 l0 = __floats2half2_rn(r00, r01);
            __half2 l1 = __floats2half2_rn(r10, r11);
            aPh[j][0] = *(uint32_t*)&h0; aPh[j][1] = *(uint32_t*)&h1;
            aPl[j][0] = *(uint32_t*)&l0; aPl[j][1] = *(uint32_t*)&l1;
        }

        // O += P V (2-pass)
#pragma unroll
        for (int kc = 0; kc < 4; kc++) {
            uint32_t Ahf[4] = {aPh[2 * kc][0], aPh[2 * kc][1],
                               aPh[2 * kc + 1][0], aPh[2 * kc + 1][1]};
            uint32_t Alf[4] = {aPl[2 * kc][0], aPl[2 * kc][1],
                               aPl[2 * kc + 1][0], aPl[2 * kc + 1][1]};
#pragma unroll
            for (int dj = 0; dj < 4; dj++) {
                uint32_t vd = sVh + (uint32_t)((kc * 16 + lrow) * AT_PITCH + dj * 16 + lkc) * 2;
                uint32_t tvh[4];
                LDSM4T(tvh, vd);
                uint32_t bh0[2] = {tvh[0], tvh[1]}, bh1[2] = {tvh[2], tvh[3]};
                mma16816(O[2 * dj],     Ahf, bh0);
                mma16816(O[2 * dj + 1], Ahf, bh1);
                mma16816(O[2 * dj],     Alf, bh0);
                mma16816(O[2 * dj + 1], Alf, bh1);
            }
        }
        __syncthreads();
    }

    // finalize
    lsum0 += __shfl_xor_sync(0xffffffffu, lsum0, 1);
    lsum0 += __shfl_xor_sync(0xffffffffu, lsum0, 2);
    lsum1 += __shfl_xor_sync(0xffffffffu, lsum1, 1);
    lsum1 += __shfl_xor_sync(0xffffffffu, lsum1, 2);
    float inv0 = 1.0f / lsum0;
    float inv1 = 1.0f / lsum1;

#pragma unroll
    for (int hh = 0; hh < 2; hh++) {
        float inv = hh ? inv1 : inv0;
        size_t orow = (size_t)(b * TT + t_base + hh * 8) * CC + h * DD + (lane & 3) * 2;
#pragma unroll
        for (int j = 0; j < 8; j++) {
            float v0 = O[j][hh * 2 + 0] * inv;
            float v1 = O[j][hh * 2 + 1] * inv;
            __half h0, l0, h1, l1;
            split2(v0, h0, l0);
            split2(v1, h1, l1);
            __half2 hp; hp.x = h0; hp.y = h1;
            __half2 lp; lp.x = l0; lp.y = l1;
            *(__half2*)(outH + orow + j * 8) = hp;
            *(__half2*)(outL + orow + j * 8) = lp;
        }
    }
}

// ---------------------------------------------------------------------------
// Fixup: rows t < first_unpadded[b] -> out = mean of V over padded positions.
// ---------------------------------------------------------------------------
__global__ __launch_bounds__(256) void fixup_kernel(
    const __half* __restrict__ qkvH,
    const __half* __restrict__ qkvL,
    const int* __restrict__ mask,
    __half* __restrict__ outH,
    __half* __restrict__ outL)
{
    int b = blockIdx.x;
    int f = g_fu[b];
    if (f == 0) return;
    int tid = threadIdx.x;
    float sum[4] = {0, 0, 0, 0};
    int cnt = 0;
    for (int s = 0; s < TT; s++) {
        if (mask[b * TT + s]) {
            cnt++;
            size_t base = (size_t)(b * TT + s) * (3 * CC) + 2 * CC + tid * 4;
#pragma unroll
            for (int e = 0; e < 4; e++)
                sum[e] += __half2float(qkvH[base + e]) +
                          __half2float(qkvL[base + e]);
        }
    }
    float invc = 1.0f / (float)cnt;
    __half mh[4], ml[4];
#pragma unroll
    for (int e = 0; e < 4; e++) split2(sum[e] * invc, mh[e], ml[e]);
    for (int t = 0; t < f; t++) {
        size_t o = (size_t)(b * TT + t) * CC + tid * 4;
#pragma unroll
        for (int e = 0; e < 4; e++) {
            outH[o + e] = mh[e];
            outL[o + e] = ml[e];
        }
    }
}

// ---------------------------------------------------------------------------
// Launch
// ---------------------------------------------------------------------------
extern "C" void kernel_launch(void* const* d_in, const int* in_sizes, int n_in,
                              void* d_out, int out_size)
{
    const float* x     = (const float*)d_in[0];
    const void*  pmask = d_in[1];
    const float* Wq    = (const float*)d_in[2];
    const float* Wk    = (const float*)d_in[3];
    const float* Wv    = (const float*)d_in[4];
    const float* Wo    = (const float*)d_in[5];
    const float* bo    = (const float*)d_in[6];
    const float* ln1_g = (const float*)d_in[7];
    const float* ln1_b = (const float*)d_in[8];
    const float* ln2_g = (const float*)d_in[9];
    const float* ln2_b = (const float*)d_in[10];
    const float* W1    = (const float*)d_in[11];
    const float* b1    = (const float*)d_in[12];
    const float* W2    = (const float*)d_in[13];
    const float* b2    = (const float*)d_in[14];
    float* out = (float*)d_out;

    void *p_proj, *p_qkvH, *p_qkvL, *p_hH, *p_hL, *p_atH, *p_atL,
         *p_h2H, *p_h2L, *p_f1H, *p_f1L, *p_wqH, *p_woH, *p_w1H, *p_w2H, *p_mask;
    cudaGetSymbolAddress(&p_proj, g_proj);
    cudaGetSymbolAddress(&p_qkvH, g_qkvH);
    cudaGetSymbolAddress(&p_qkvL, g_qkvL);
    cudaGetSymbolAddress(&p_hH,   g_hH);
    cudaGetSymbolAddress(&p_hL,   g_hL);
    cudaGetSymbolAddress(&p_atH,  g_atH);
    cudaGetSymbolAddress(&p_atL,  g_atL);
    cudaGetSymbolAddress(&p_h2H,  g_h2H);
    cudaGetSymbolAddress(&p_h2L,  g_h2L);
    cudaGetSymbolAddress(&p_f1H,  g_f1H);
    cudaGetSymbolAddress(&p_f1L,  g_f1L);
    cudaGetSymbolAddress(&p_wqH,  g_wqH);
    cudaGetSymbolAddress(&p_woH,  g_woH);
    cudaGetSymbolAddress(&p_w1H,  g_w1H);
    cudaGetSymbolAddress(&p_w2H,  g_w2H);
    cudaGetSymbolAddress(&p_mask, g_mask);

    cudaFuncSetAttribute(gemm_mma, cudaFuncAttributeMaxDynamicSharedMemorySize, GEMM_SMEM);
    cudaFuncSetAttribute(attn_mma, cudaFuncAttributeMaxDynamicSharedMemorySize, ATT_SMEM);

    // 1. mask + first-unpadded
    mask_expand_kernel<<<1, 256>>>(pmask, (int*)p_mask);
    // 2. weight prep (fp16, hi only)
    pack_qkv_kernel<<<(3 * CC * CC + 255) / 256, 256>>>(Wq, Wk, Wv, (__half*)p_wqH);
    tsplit_kernel<<<dim3(CC / 32, CC / 32), dim3(32, 8)>>>(Wo, (__half*)p_woH, CC, CC);
    tsplit_kernel<<<dim3(FF / 32, CC / 32), dim3(32, 8)>>>(W1, (__half*)p_w1H, CC, FF);
    tsplit_kernel<<<dim3(CC / 32, FF / 32), dim3(32, 8)>>>(W2, (__half*)p_w2H, FF, CC);
    // 3. LN1
    ln_split_kernel<<<MR, 256>>>(x, ln1_g, ln1_b, (__half*)p_hH, (__half*)p_hL);
    // 4. QKV gemm
    gemm_mma<<<dim3(3 * CC / 128, MR / 128), 256, GEMM_SMEM>>>(
        (__half*)p_hH, (__half*)p_hL, (__half*)p_wqH, nullptr,
        nullptr, (__half*)p_qkvH, (__half*)p_qkvL, 3 * CC, CC, 0);
    // 5. flash attention + fixup
    attn_mma<<<dim3(TT / 128, BB * HH), 256, ATT_SMEM>>>(
        (const __half*)p_qkvH, (const __half*)p_qkvL, (const int*)p_mask,
        (__half*)p_atH, (__half*)p_atL);
    fixup_kernel<<<BB, 256>>>(
        (const __half*)p_qkvH, (const __half*)p_qkvL, (const int*)p_mask,
        (__half*)p_atH, (__half*)p_atL);
    // 6. Wo projection
    gemm_mma<<<dim3(CC / 128, MR / 128), 256, GEMM_SMEM>>>(
        (__half*)p_atH, (__half*)p_atL, (__half*)p_woH, bo,
        (float*)p_proj, nullptr, nullptr, CC, CC, 0);
    // 7. LN2
    ln_split_kernel<<<MR, 256>>>((const float*)p_proj, ln2_g, ln2_b,
                                 (__half*)p_h2H, (__half*)p_h2L);
    // 8. FFN1 + relu
    gemm_mma<<<dim3(FF / 128, MR / 128), 256, GEMM_SMEM>>>(
        (__half*)p_h2H, (__half*)p_h2L, (__half*)p_w1H, b1,
        nullptr, (__half*)p_f1H, (__half*)p_f1L, FF, CC, 1);
    // 9. FFN2 -> d_out
    gemm_mma<<<dim3(CC / 128, MR / 128), 256, GEMM_SMEM>>>(
        (__half*)p_f1H, (__half*)p_f1L, (__half*)p_w2H, b2,
        out, nullptr, nullptr, CC, FF, 0);
}

// round 7
// speedup vs baseline: 3.0878x; 1.0788x over previous
#include <cuda_runtime.h>
#include <cuda_fp16.h>
#include <cstdint>
#include <math.h>

// Problem dims
#define BB 4
#define TT 1024
#define CC 1024
#define HH 16
#define DD 64
#define FF 4096
#define MR 4096   // B*T

// ---------------------------------------------------------------------------
// Scratch (static device globals)
// ---------------------------------------------------------------------------
__device__ __align__(256) float g_proj[MR * CC];
__device__ __align__(256) __half g_qkvH[MR * 3 * CC];
__device__ __align__(256) __half g_qkvL[MR * 3 * CC];
__device__ __align__(256) __half g_hH [MR * CC];
__device__ __align__(256) __half g_hL [MR * CC];
__device__ __align__(256) __half g_atH[MR * CC];
__device__ __align__(256) __half g_atL[MR * CC];
__device__ __align__(256) __half g_h2H[MR * CC];
__device__ __align__(256) __half g_h2L[MR * CC];
__device__ __align__(256) __half g_f1H[MR * FF];
__device__ __align__(256) __half g_f1L[MR * FF];
__device__ __align__(256) __half g_wqH[3 * CC * CC];
__device__ __align__(256) __half g_woH[CC * CC];
__device__ __align__(256) __half g_w1H[FF * CC];
__device__ __align__(256) __half g_w2H[CC * FF];
__device__ int g_mask[MR];
__device__ int g_fu[BB];

// ---------------------------------------------------------------------------
// Helpers
// ---------------------------------------------------------------------------
__device__ __forceinline__ uint32_t smem_u32(const void* p) {
    uint32_t a;
    asm("{ .reg .u64 t; cvta.to.shared.u64 t, %1; cvt.u32.u64 %0, t; }" : "=r"(a) : "l"(p));
    return a;
}
__device__ __forceinline__ void cp16(uint32_t s, const void* g) {
    asm volatile("cp.async.cg.shared.global [%0], [%1], 16;" :: "r"(s), "l"(g));
}
#define CP_COMMIT() asm volatile("cp.async.commit_group;" ::: "memory")
#define CP_WAIT2()  asm volatile("cp.async.wait_group 2;"  ::: "memory")
#define CP_WAIT1()  asm volatile("cp.async.wait_group 1;"  ::: "memory")
#define CP_WAIT0()  asm volatile("cp.async.wait_group 0;"  ::: "memory")

#define LDSM4(r, addr) \
    asm volatile("ldmatrix.sync.aligned.m8n8.x4.shared.b16 {%0,%1,%2,%3}, [%4];" \
        : "=r"((r)[0]), "=r"((r)[1]), "=r"((r)[2]), "=r"((r)[3]) : "r"(addr))
#define LDSM4T(r, addr) \
    asm volatile("ldmatrix.sync.aligned.m8n8.x4.trans.shared.b16 {%0,%1,%2,%3}, [%4];" \
        : "=r"((r)[0]), "=r"((r)[1]), "=r"((r)[2]), "=r"((r)[3]) : "r"(addr))

__device__ __forceinline__ void mma16816(float* c, const uint32_t* a, const uint32_t* b) {
    asm volatile("mma.sync.aligned.m16n8k16.row.col.f32.f16.f16.f32 "
        "{%0,%1,%2,%3}, {%4,%5,%6,%7}, {%8,%9}, {%0,%1,%2,%3};"
        : "+f"(c[0]), "+f"(c[1]), "+f"(c[2]), "+f"(c[3])
        : "r"(a[0]), "r"(a[1]), "r"(a[2]), "r"(a[3]), "r"(b[0]), "r"(b[1]));
}

__device__ __forceinline__ void split2(float v, __half& h, __half& l) {
    h = __float2half_rn(v);
    l = __float2half_rn(v - __half2float(h));
}
__device__ __forceinline__ float fex2(float x) {
    float r;
    asm("ex2.approx.ftz.f32 %0, %1;" : "=f"(r) : "f"(x));
    return r;
}

// ---------------------------------------------------------------------------
// Mask classify + expand + first-unpadded per batch
// ---------------------------------------------------------------------------
__global__ void mask_expand_kernel(const void* __restrict__ pm, int* __restrict__ out)
{
    int tid = threadIdx.x;
    if (tid < BB) g_fu[tid] = TT;
    const unsigned* w = (const unsigned*)pm;
    int li = 0, lf = 0;
    for (int i = tid; i < 1024; i += 256) {
        unsigned v = w[i];
        li |= (v > 1u);
        lf |= (v != 0u && v != 0x3F800000u);
    }
    int not_int = __syncthreads_or(li);
    int not_flt = __syncthreads_or(lf);
    int cls = (!not_int) ? 0 : ((!not_flt) ? 1 : 2);
    for (int i = tid; i < MR; i += 256) {
        int m;
        if (cls == 0)      m = (((const int*)pm)[i] != 0);
        else if (cls == 1) m = (((const float*)pm)[i] != 0.0f);
        else               m = (((const unsigned char*)pm)[i] != 0);
        out[i] = m;
        if (!m) atomicMin(&g_fu[i >> 10], i & 1023);
    }
}

// ---------------------------------------------------------------------------
// Pack Wq/Wk/Wv (H,C,D) -> transposed (3C, C) fp16
// ---------------------------------------------------------------------------
__global__ void pack_qkv_kernel(const float* __restrict__ Wq,
                                const float* __restrict__ Wk,
                                const float* __restrict__ Wv,
                                __half* __restrict__ oh)
{
    int idx = blockIdx.x * blockDim.x + threadIdx.x;
    if (idx >= 3 * CC * CC) return;
    int j = idx / CC;
    int c = idx % CC;
    const float* W = (j < CC) ? Wq : (j < 2 * CC) ? Wk : Wv;
    int jj = j & (CC - 1);
    int h = jj >> 6, d = jj & 63;
    oh[idx] = __float2half_rn(W[(h * CC + c) * DD + d]);
}

// ---------------------------------------------------------------------------
// Tiled transpose: in (R, Cn) fp32 -> out (Cn, R) fp16
// ---------------------------------------------------------------------------
__global__ void tsplit_kernel(const float* __restrict__ in,
                              __half* __restrict__ oh,
                              int R, int Cn)
{
    __shared__ float t[32][33];
    int c0 = blockIdx.x * 32, r0 = blockIdx.y * 32;
    int x = threadIdx.x, y = threadIdx.y;
#pragma unroll
    for (int i = 0; i < 32; i += 8)
        t[y + i][x] = in[(size_t)(r0 + y + i) * Cn + c0 + x];
    __syncthreads();
#pragma unroll
    for (int i = 0; i < 32; i += 8)
        oh[(size_t)(c0 + y + i) * R + r0 + x] = __float2half_rn(t[x][y + i]);
}

// ---------------------------------------------------------------------------
// LayerNorm + split (fp16 hi/lo)
// ---------------------------------------------------------------------------
__global__ __launch_bounds__(256) void ln_split_kernel(const float* __restrict__ x,
                                                       const float* __restrict__ g,
                                                       const float* __restrict__ b,
                                                       __half* __restrict__ oh,
                                                       __half* __restrict__ ol)
{
    int row = blockIdx.x, tid = threadIdx.x;
    const float* xr = x + (size_t)row * CC;
    float v[4];
    float s = 0.f, ss = 0.f;
#pragma unroll
    for (int i = 0; i < 4; i++) {
        v[i] = xr[tid + i * 256];
        s += v[i];
        ss += v[i] * v[i];
    }
#pragma unroll
    for (int o = 16; o; o >>= 1) {
        s  += __shfl_xor_sync(0xffffffffu, s,  o);
        ss += __shfl_xor_sync(0xffffffffu, ss, o);
    }
    __shared__ float ws[8], wss[8];
    __shared__ float s_m, s_r;
    int wid = tid >> 5;
    if ((tid & 31) == 0) { ws[wid] = s; wss[wid] = ss; }
    __syncthreads();
    if (tid == 0) {
        float S = 0.f, SS = 0.f;
        for (int i = 0; i < 8; i++) { S += ws[i]; SS += wss[i]; }
        float m = S * (1.0f / CC);
        float var = SS * (1.0f / CC) - m * m;
        s_m = m;
        s_r = rsqrtf(var + 1e-5f);
    }
    __syncthreads();
    float m = s_m, r = s_r;
#pragma unroll
    for (int i = 0; i < 4; i++) {
        int c = tid + i * 256;
        float o = (v[i] - m) * r * g[c] + b[c];
        __half hh, ll; split2(o, hh, ll);
        size_t idx = (size_t)row * CC + c;
        oh[idx] = hh; ol[idx] = ll;
    }
}

// ---------------------------------------------------------------------------
// fp16 2-pass GEMM v2: D = (Ah+Al)(M,K) @ Bh^T, B stored (N,K) fp16.
// CTA 128x256, K-chunk 64, 8 warps (warp tile 64x64), 3-stage cp.async.
// ---------------------------------------------------------------------------
#define PITCH 72
#define A_TILE_B (128 * PITCH * 2)          // 18432
#define B_TILE_B (256 * PITCH * 2)          // 36864
#define STAGE_B (2 * A_TILE_B + B_TILE_B)   // 73728
#define NSTAGE 3
#define GEMM_SMEM (NSTAGE * STAGE_B)        // 221184

__global__ __launch_bounds__(256, 1) void gemm_mma(
    const __half* __restrict__ Ah, const __half* __restrict__ Al,
    const __half* __restrict__ Bh,
    const float* __restrict__ bias,
    float* __restrict__ outF,
    __half* __restrict__ outH, __half* __restrict__ outL,
    int Ntot, int Ktot, int relu)
{
    extern __shared__ __align__(128) char smem[];
    const uint32_t sb0 = smem_u32(smem);
    int tid = threadIdx.x, lane = tid & 31, w = tid >> 5;
    int bm = blockIdx.y * 128, bn = blockIdx.x * 256;
    int wm = (w & 1) * 64, wn = (w >> 1) * 64;
    int nk = Ktot >> 6;

    float acc[4][8][4];
#pragma unroll
    for (int i = 0; i < 4; i++)
#pragma unroll
        for (int j = 0; j < 8; j++)
#pragma unroll
            for (int e = 0; e < 4; e++) acc[i][j][e] = 0.0f;

    auto load_stage = [&](int st, int kc) {
        uint32_t sb = sb0 + st * STAGE_B;
#pragma unroll
        for (int i = 0; i < 16; i++) {
            int idx = tid + i * 256;
            int c = (idx & 7) * 8;
            if (i < 4) {              // Ah: idx 0..1023
                int r = idx >> 3;
                cp16(sb + (uint32_t)(r * PITCH + c) * 2,
                     Ah + (size_t)(bm + r) * Ktot + kc + c);
            } else if (i < 8) {       // Al: idx 1024..2047
                int r = (idx - 1024) >> 3;
                cp16(sb + A_TILE_B + (uint32_t)(r * PITCH + c) * 2,
                     Al + (size_t)(bm + r) * Ktot + kc + c);
            } else {                  // Bh: idx 2048..4095
                int r = (idx - 2048) >> 3;
                cp16(sb + 2 * A_TILE_B + (uint32_t)(r * PITCH + c) * 2,
                     Bh + (size_t)(bn + r) * Ktot + kc + c);
            }
        }
    };

    load_stage(0, 0);
    CP_COMMIT();
    if (nk > 1) { load_stage(1, 64); CP_COMMIT(); }

    int lrow = lane & 15;
    int lk = (lane >> 4) * 8;

    for (int kc = 0; kc < nk; kc++) {
        if (kc + 2 < nk) {
            load_stage((kc + 2) % 3, (kc + 2) * 64);
            CP_COMMIT();
            CP_WAIT2();
        } else {
            CP_WAIT0();
        }
        __syncthreads();

        uint32_t sb = sb0 + (kc % 3) * STAGE_B;
#pragma unroll
        for (int ks = 0; ks < 4; ks++) {
            int k0 = ks * 16;
            uint32_t ah[4][4], al[4][4], bh[8][2];
#pragma unroll
            for (int i = 0; i < 4; i++) {
                uint32_t ad = sb + (uint32_t)((wm + i * 16 + lrow) * PITCH + k0 + lk) * 2;
                LDSM4(ah[i], ad);
                LDSM4(al[i], ad + A_TILE_B);
            }
#pragma unroll
            for (int jj = 0; jj < 4; jj++) {
                uint32_t bd = sb + 2 * A_TILE_B +
                              (uint32_t)((wn + jj * 16 + lrow) * PITCH + k0 + lk) * 2;
                uint32_t t[4];
                LDSM4(t, bd);
                bh[jj * 2][0] = t[0]; bh[jj * 2][1] = t[2];
                bh[jj * 2 + 1][0] = t[1]; bh[jj * 2 + 1][1] = t[3];
            }
#pragma unroll
            for (int i = 0; i < 4; i++)
#pragma unroll
                for (int j = 0; j < 8; j++)
                    mma16816(acc[i][j], ah[i], bh[j]);
#pragma unroll
            for (int i = 0; i < 4; i++)
#pragma unroll
                for (int j = 0; j < 8; j++)
                    mma16816(acc[i][j], al[i], bh[j]);
        }
        __syncthreads();
    }

#pragma unroll
    for (int i = 0; i < 4; i++) {
        int r0 = bm + wm + i * 16 + (lane >> 2);
#pragma unroll
        for (int j = 0; j < 8; j++) {
            int c = bn + wn + j * 8 + (lane & 3) * 2;
            float bx0 = bias ? bias[c] : 0.0f;
            float bx1 = bias ? bias[c + 1] : 0.0f;
#pragma unroll
            for (int hh = 0; hh < 2; hh++) {
                int r = r0 + hh * 8;
                float v0 = acc[i][j][hh * 2 + 0] + bx0;
                float v1 = acc[i][j][hh * 2 + 1] + bx1;
                if (relu) { v0 = fmaxf(v0, 0.0f); v1 = fmaxf(v1, 0.0f); }
                size_t o = (size_t)r * Ntot + c;
                if (outF) {
                    outF[o] = v0;
                    outF[o + 1] = v1;
                } else {
                    __half h0, l0, h1, l1;
                    split2(v0, h0, l0);
                    split2(v1, h1, l1);
                    __half2 hp; hp.x = h0; hp.y = h1;
                    __half2 lp; lp.x = l0; lp.y = l1;
                    *(__half2*)(outH + o) = hp;
                    *(__half2*)(outL + o) = lp;
                }
            }
        }
    }
}

// ---------------------------------------------------------------------------
// fp16 flash attention (R6 structure; qi reversed for heavy-first scheduling)
// ---------------------------------------------------------------------------
#define AT_PITCH 72
#define AQ_TILEB (128 * AT_PITCH * 2)     // 18432
#define AKV_TILEB (64 * AT_PITCH * 2)     // 9216
#define SMASK_OFF (2 * AQ_TILEB + 4 * AKV_TILEB)   // 73728
#define ATT_SMEM (SMASK_OFF + 2 * 64 * 4)          // 74240

__global__ __launch_bounds__(256) void attn_mma(
    const __half* __restrict__ qkvH,
    const __half* __restrict__ qkvL,
    const int* __restrict__ mask,
    __half* __restrict__ outH,
    __half* __restrict__ outL)
{
    extern __shared__ __align__(128) char smem[];
    const uint32_t sb = smem_u32(smem);
    const uint32_t sQh = sb, sQl = sb + AQ_TILEB;

    int qi = (int)gridDim.x - 1 - (int)blockIdx.x;   // heavy blocks first
    int bh = blockIdx.y;
    int b = bh >> 4, h = bh & 15;
    int tid = threadIdx.x, lane = tid & 31, w = tid >> 5;
    int wq = w * 16;
    int lrow = lane & 15, lkc = (lane >> 4) * 8;

    const size_t rowbase = (size_t)(b * TT) * (3 * CC) + h * DD;
    const int* gmask = mask + b * TT;
    int* smask = (int*)(smem + SMASK_OFF);

    // Q tile (hi+lo)
#pragma unroll
    for (int i = 0; i < 4; i++) {
        int idx = tid + i * 256;
        int r = idx >> 3, ch = (idx & 7) * 8;
        uint32_t so = (uint32_t)(r * AT_PITCH + ch) * 2;
        size_t go = rowbase + (size_t)(qi * 128 + r) * (3 * CC) + ch;
        cp16(sQh + so, qkvH + go);
        cp16(sQl + so, qkvL + go);
    }

    auto load_stage = [&](int sj) {
        int st = sj & 1;
        uint32_t base = sb + 2 * AQ_TILEB + st * (2 * AKV_TILEB);
#pragma unroll
        for (int i = 0; i < 4; i++) {
            int idx = tid + i * 256;
            int tile = idx >> 9;
            int rem = idx & 511;
            int r = rem >> 3, ch = (rem & 7) * 8;
            uint32_t so = base + tile * AKV_TILEB + (uint32_t)(r * AT_PITCH + ch) * 2;
            size_t gk = rowbase + (size_t)(sj * 64 + r) * (3 * CC) + CC + ch;
            if (tile == 0) cp16(so, qkvH + gk);
            else           cp16(so, qkvH + gk + CC);
        }
        if (tid < 16)
            cp16(sb + SMASK_OFF + st * 256 + tid * 16, gmask + sj * 64 + tid * 4);
    };

    int ns = 2 * qi + 2;
    load_stage(0);
    CP_COMMIT();

    float O[8][4];
#pragma unroll
    for (int j = 0; j < 8; j++)
#pragma unroll
        for (int e = 0; e < 4; e++) O[j][e] = 0.0f;
    float lsum0 = 0.0f, lsum1 = 0.0f;

    const float csc = 0.0450842200f;   // log2(e) / 32
    const int t_base = qi * 128 + wq + (lane >> 2);

    for (int sj = 0; sj < ns; sj++) {
        int cur = sj & 1;
        if (sj + 1 < ns) {
            load_stage(sj + 1);
            CP_COMMIT();
            CP_WAIT1();
        } else {
            CP_WAIT0();
        }
        __syncthreads();

        uint32_t kvb = sb + 2 * AQ_TILEB + cur * (2 * AKV_TILEB);
        uint32_t sKh = kvb, sVh = kvb + AKV_TILEB;
        const int* mrow = smask + cur * 64;

        // S = Q K^T (2-pass)
        float S[8][4];
#pragma unroll
        for (int j = 0; j < 8; j++)
#pragma unroll
            for (int e = 0; e < 4; e++) S[j][e] = 0.0f;

#pragma unroll
        for (int ks = 0; ks < 4; ks++) {
            uint32_t qa[4], ql[4];
            uint32_t ad = sQh + (uint32_t)((wq + lrow) * AT_PITCH + ks * 16 + lkc) * 2;
            LDSM4(qa, ad);
            LDSM4(ql, ad + AQ_TILEB);
#pragma unroll
            for (int nj = 0; nj < 4; nj++) {
                uint32_t bd = sKh + (uint32_t)((nj * 16 + lrow) * AT_PITCH + ks * 16 + lkc) * 2;
                uint32_t th[4];
                LDSM4(th, bd);
                uint32_t bh0[2] = {th[0], th[2]}, bh1[2] = {th[1], th[3]};
                mma16816(S[2 * nj],     qa, bh0);
                mma16816(S[2 * nj + 1], qa, bh1);
                mma16816(S[2 * nj],     ql, bh0);
                mma16816(S[2 * nj + 1], ql, bh1);
            }
        }

        // mask + exp2
#pragma unroll
        for (int j = 0; j < 8; j++) {
            int s0 = j * 8 + (lane & 3) * 2;
#pragma unroll
            for (int e = 0; e < 4; e++) {
                int s_l = s0 + (e & 1);
                int s_g = sj * 64 + s_l;
                int t_g = t_base + (e >> 1) * 8;
                float v = S[j][e] * csc;
                if (mrow[s_l] || (s_g > t_g)) v = -1e9f;
                S[j][e] = fex2(v);
            }
            lsum0 += S[j][0] + S[j][1];
            lsum1 += S[j][2] + S[j][3];
        }

        // pack P (hi/lo fp16)
        uint32_t aPh[8][2], aPl[8][2];
#pragma unroll
        for (int j = 0; j < 8; j++) {
            __half2 h0 = __floats2half2_rn(S[j][0], S[j][1]);
            __half2 h1 = __floats2half2_rn(S[j][2], S[j][3]);
            float r00 = S[j][0] - __half2float(h0.x);
            float r01 = S[j][1] - __half2float(h0.y);
            float r10 = S[j][2] - __half2float(h1.x);
            float r11 = S[j][3] - __half2float(h1.y);
            __half2 l0 = __floats2half2_rn(r00, r01);
            __half2 l1 = __floats2half2_rn(r10, r11);
            aPh[j][0] = *(uint32_t*)&h0; aPh[j][1] = *(uint32_t*)&h1;
            aPl[j][0] = *(uint32_t*)&l0; aPl[j][1] = *(uint32_t*)&l1;
        }

        // O += P V (2-pass)
#pragma unroll
        for (int kc = 0; kc < 4; kc++) {
            uint32_t Ahf[4] = {aPh[2 * kc][0], aPh[2 * kc][1],
                               aPh[2 * kc + 1][0], aPh[2 * kc + 1][1]};
            uint32_t Alf[4] = {aPl[2 * kc][0], aPl[2 * kc][1],
                               aPl[2 * kc + 1][0], aPl[2 * kc + 1][1]};
#pragma unroll
            for (int dj = 0; dj < 4; dj++) {
                uint32_t vd = sVh + (uint32_t)((kc * 16 + lrow) * AT_PITCH + dj * 16 + lkc) * 2;
                uint32_t tvh[4];
                LDSM4T(tvh, vd);
                uint32_t bh0[2] = {tvh[0], tvh[1]}, bh1[2] = {tvh[2], tvh[3]};
                mma16816(O[2 * dj],     Ahf, bh0);
                mma16816(O[2 * dj + 1], Ahf, bh1);
                mma16816(O[2 * dj],     Alf, bh0);
                mma16816(O[2 * dj + 1], Alf, bh1);
            }
        }
        __syncthreads();
    }

    // finalize
    lsum0 += __shfl_xor_sync(0xffffffffu, lsum0, 1);
    lsum0 += __shfl_xor_sync(0xffffffffu, lsum0, 2);
    lsum1 += __shfl_xor_sync(0xffffffffu, lsum1, 1);
    lsum1 += __shfl_xor_sync(0xffffffffu, lsum1, 2);
    float inv0 = 1.0f / lsum0;
    float inv1 = 1.0f / lsum1;

#pragma unroll
    for (int hh = 0; hh < 2; hh++) {
        float inv = hh ? inv1 : inv0;
        size_t orow = (size_t)(b * TT + t_base + hh * 8) * CC + h * DD + (lane & 3) * 2;
#pragma unroll
        for (int j = 0; j < 8; j++) {
            float v0 = O[j][hh * 2 + 0] * inv;
            float v1 = O[j][hh * 2 + 1] * inv;
            __half h0, l0, h1, l1;
            split2(v0, h0, l0);
            split2(v1, h1, l1);
            __half2 hp; hp.x = h0; hp.y = h1;
            __half2 lp; lp.x = l0; lp.y = l1;
            *(__half2*)(outH + orow + j * 8) = hp;
            *(__half2*)(outL + orow + j * 8) = lp;
        }
    }
}

// ---------------------------------------------------------------------------
// Fixup: rows t < first_unpadded[b] -> out = mean of V over padded positions.
// ---------------------------------------------------------------------------
__global__ __launch_bounds__(256) void fixup_kernel(
    const __half* __restrict__ qkvH,
    const __half* __restrict__ qkvL,
    const int* __restrict__ mask,
    __half* __restrict__ outH,
    __half* __restrict__ outL)
{
    int b = blockIdx.x;
    int f = g_fu[b];
    if (f == 0) return;
    int tid = threadIdx.x;
    float sum[4] = {0, 0, 0, 0};
    int cnt = 0;
    for (int s = 0; s < TT; s++) {
        if (mask[b * TT + s]) {
            cnt++;
            size_t base = (size_t)(b * TT + s) * (3 * CC) + 2 * CC + tid * 4;
#pragma unroll
            for (int e = 0; e < 4; e++)
                sum[e] += __half2float(qkvH[base + e]) +
                          __half2float(qkvL[base + e]);
        }
    }
    float invc = 1.0f / (float)cnt;
    __half mh[4], ml[4];
#pragma unroll
    for (int e = 0; e < 4; e++) split2(sum[e] * invc, mh[e], ml[e]);
    for (int t = 0; t < f; t++) {
        size_t o = (size_t)(b * TT + t) * CC + tid * 4;
#pragma unroll
        for (int e = 0; e < 4; e++) {
            outH[o + e] = mh[e];
            outL[o + e] = ml[e];
        }
    }
}

// ---------------------------------------------------------------------------
// Launch
// ---------------------------------------------------------------------------
extern "C" void kernel_launch(void* const* d_in, const int* in_sizes, int n_in,
                              void* d_out, int out_size)
{
    const float* x     = (const float*)d_in[0];
    const void*  pmask = d_in[1];
    const float* Wq    = (const float*)d_in[2];
    const float* Wk    = (const float*)d_in[3];
    const float* Wv    = (const float*)d_in[4];
    const float* Wo    = (const float*)d_in[5];
    const float* bo    = (const float*)d_in[6];
    const float* ln1_g = (const float*)d_in[7];
    const float* ln1_b = (const float*)d_in[8];
    const float* ln2_g = (const float*)d_in[9];
    const float* ln2_b = (const float*)d_in[10];
    const float* W1    = (const float*)d_in[11];
    const float* b1    = (const float*)d_in[12];
    const float* W2    = (const float*)d_in[13];
    const float* b2    = (const float*)d_in[14];
    float* out = (float*)d_out;

    void *p_proj, *p_qkvH, *p_qkvL, *p_hH, *p_hL, *p_atH, *p_atL,
         *p_h2H, *p_h2L, *p_f1H, *p_f1L, *p_wqH, *p_woH, *p_w1H, *p_w2H, *p_mask;
    cudaGetSymbolAddress(&p_proj, g_proj);
    cudaGetSymbolAddress(&p_qkvH, g_qkvH);
    cudaGetSymbolAddress(&p_qkvL, g_qkvL);
    cudaGetSymbolAddress(&p_hH,   g_hH);
    cudaGetSymbolAddress(&p_hL,   g_hL);
    cudaGetSymbolAddress(&p_atH,  g_atH);
    cudaGetSymbolAddress(&p_atL,  g_atL);
    cudaGetSymbolAddress(&p_h2H,  g_h2H);
    cudaGetSymbolAddress(&p_h2L,  g_h2L);
    cudaGetSymbolAddress(&p_f1H,  g_f1H);
    cudaGetSymbolAddress(&p_f1L,  g_f1L);
    cudaGetSymbolAddress(&p_wqH,  g_wqH);
    cudaGetSymbolAddress(&p_woH,  g_woH);
    cudaGetSymbolAddress(&p_w1H,  g_w1H);
    cudaGetSymbolAddress(&p_w2H,  g_w2H);
    cudaGetSymbolAddress(&p_mask, g_mask);

    cudaFuncSetAttribute(gemm_mma, cudaFuncAttributeMaxDynamicSharedMemorySize, GEMM_SMEM);
    cudaFuncSetAttribute(attn_mma, cudaFuncAttributeMaxDynamicSharedMemorySize, ATT_SMEM);

    // 1. mask + first-unpadded
    mask_expand_kernel<<<1, 256>>>(pmask, (int*)p_mask);
    // 2. weight prep (fp16)
    pack_qkv_kernel<<<(3 * CC * CC + 255) / 256, 256>>>(Wq, Wk, Wv, (__half*)p_wqH);
    tsplit_kernel<<<dim3(CC / 32, CC / 32), dim3(32, 8)>>>(Wo, (__half*)p_woH, CC, CC);
    tsplit_kernel<<<dim3(FF / 32, CC / 32), dim3(32, 8)>>>(W1, (__half*)p_w1H, CC, FF);
    tsplit_kernel<<<dim3(CC / 32, FF / 32), dim3(32, 8)>>>(W2, (__half*)p_w2H, FF, CC);
    // 3. LN1
    ln_split_kernel<<<MR, 256>>>(x, ln1_g, ln1_b, (__half*)p_hH, (__half*)p_hL);
    // 4. QKV gemm
    gemm_mma<<<dim3(3 * CC / 256, MR / 128), 256, GEMM_SMEM>>>(
        (__half*)p_hH, (__half*)p_hL, (__half*)p_wqH, nullptr,
        nullptr, (__half*)p_qkvH, (__half*)p_qkvL, 3 * CC, CC, 0);
    // 5. flash attention + fixup
    attn_mma<<<dim3(TT / 128, BB * HH), 256, ATT_SMEM>>>(
        (const __half*)p_qkvH, (const __half*)p_qkvL, (const int*)p_mask,
        (__half*)p_atH, (__half*)p_atL);
    fixup_kernel<<<BB, 256>>>(
        (const __half*)p_qkvH, (const __half*)p_qkvL, (const int*)p_mask,
        (__half*)p_atH, (__half*)p_atL);
    // 6. Wo projection
    gemm_mma<<<dim3(CC / 256, MR / 128), 256, GEMM_SMEM>>>(
        (__half*)p_atH, (__half*)p_atL, (__half*)p_woH, bo,
        (float*)p_proj, nullptr, nullptr, CC, CC, 0);
    // 7. LN2
    ln_split_kernel<<<MR, 256>>>((const float*)p_proj, ln2_g, ln2_b,
                                 (__half*)p_h2H, (__half*)p_h2L);
    // 8. FFN1 + relu
    gemm_mma<<<dim3(FF / 256, MR / 128), 256, GEMM_SMEM>>>(
        (__half*)p_h2H, (__half*)p_h2L, (__half*)p_w1H, b1,
        nullptr, (__half*)p_f1H, (__half*)p_f1L, FF, CC, 1);
    // 9. FFN2 -> d_out
    gemm_mma<<<dim3(CC / 256, MR / 128), 256, GEMM_SMEM>>>(
        (__half*)p_f1H, (__half*)p_f1L, (__half*)p_w2H, b2,
        out, nullptr, nullptr, CC, FF, 0);
}